// round 13
// baseline (speedup 1.0000x reference)
#include <cuda_runtime.h>
#include <cuda_fp16.h>
#include <math.h>
#include <stdint.h>

// Problem constants
#define Bsz 2
#define Lx  2048
#define Cx  1024
#define Hx  16
#define Dx  64
#define Mrows (Bsz*Lx)      // 4096

// ---------------- scratch (__device__ globals: alloc-free) ----------------
__device__ float g_x1 [Mrows * Cx];

__device__ __half g_h  [Mrows * Cx];
__device__ __half g_y  [Mrows * Cx];
__device__ __half g_fc [Mrows * 4 * Cx];

// attention operands, [B,H,L,D]
__device__ __half g_q  [Mrows * Cx];
__device__ __half g_kh [Mrows * Cx];
__device__ __half g_kls[Mrows * Cx];
__device__ __half g_vh [Mrows * Cx];
__device__ __half g_vls[Mrows * Cx];

// weights: hi + scaled lo
__device__ __half g_wa_h [Cx * 3 * Cx];
__device__ __half g_wa_l [Cx * 3 * Cx];
__device__ __half g_wp_h [Cx * Cx];
__device__ __half g_wp_l [Cx * Cx];
__device__ __half g_wf_h [Cx * 4 * Cx];
__device__ __half g_wf_l [Cx * 4 * Cx];
__device__ __half g_w2_h [4 * Cx * Cx];
__device__ __half g_w2_l [4 * Cx * Cx];

// ================= helpers ==========================
__device__ __forceinline__ uint32_t smem_u32(const void* p) {
    uint32_t a;
    asm("{ .reg .u64 t; cvta.to.shared.u64 t, %1; cvt.u32.u64 %0, t; }"
        : "=r"(a) : "l"(p));
    return a;
}
__device__ __forceinline__ uint32_t pack_h(float a, float b) {
    __half2 h = __floats2half2_rn(a, b);
    return *(uint32_t*)&h;
}
__device__ __forceinline__ uint32_t pack_ls(float a, float b) {
    float ha = __half2float(__float2half_rn(a));
    float hb = __half2float(__float2half_rn(b));
    __half2 h = __floats2half2_rn((a - ha) * 2048.f, (b - hb) * 2048.f);
    return *(uint32_t*)&h;
}
__device__ __forceinline__ uint32_t hscale(uint32_t x) {
    uint32_t r;
    asm("mul.rn.f16x2 %0, %1, %2;" : "=r"(r) : "r"(x), "r"(0x10001000u));
    return r;
}

__device__ __forceinline__ void cp16(uint32_t dst, const void* src) {
    asm volatile("cp.async.cg.shared.global [%0], [%1], 16;"
                 :: "r"(dst), "l"(src));
}
#define CP_COMMIT() asm volatile("cp.async.commit_group;" ::: "memory")
#define CP_WAIT0()  asm volatile("cp.async.wait_group 0;" ::: "memory")

__device__ __forceinline__ void ldsm4(uint32_t (&r)[4], uint32_t addr) {
    asm volatile("ldmatrix.sync.aligned.m8n8.x4.shared.b16 {%0,%1,%2,%3}, [%4];"
                 : "=r"(r[0]), "=r"(r[1]), "=r"(r[2]), "=r"(r[3]) : "r"(addr));
}
__device__ __forceinline__ void ldsm4t(uint32_t (&r)[4], uint32_t addr) {
    asm volatile("ldmatrix.sync.aligned.m8n8.x4.trans.shared.b16 {%0,%1,%2,%3}, [%4];"
                 : "=r"(r[0]), "=r"(r[1]), "=r"(r[2]), "=r"(r[3]) : "r"(addr));
}
__device__ __forceinline__ void mma_f16(float (&c)[4], const uint32_t (&a)[4],
                                        uint32_t b0, uint32_t b1) {
    asm volatile(
        "mma.sync.aligned.m16n8k16.row.col.f32.f16.f16.f32 "
        "{%0,%1,%2,%3},{%4,%5,%6,%7},{%8,%9},{%0,%1,%2,%3};"
        : "+f"(c[0]), "+f"(c[1]), "+f"(c[2]), "+f"(c[3])
        : "r"(a[0]), "r"(a[1]), "r"(a[2]), "r"(a[3]), "r"(b0), "r"(b1));
}

__device__ __forceinline__ float gelu_f(float x) {
    float x3 = x * x * x;
    float t  = tanhf(0.7978845608028654f * (x + 0.044715f * x3));
    return 0.5f * x * (1.0f + t);
}

// exp2 on the FMA pipe
__device__ __forceinline__ float pexp2(float t) {
    t = fmaxf(t, -126.f);
    float k  = t + 12582912.f;
    int   i  = __float_as_int(k) - 0x4B400000;
    float fi = k - 12582912.f;
    float f  = t - fi;
    float p  = 1.3333558e-3f;
    p = fmaf(p, f, 9.6181291e-3f);
    p = fmaf(p, f, 5.5504109e-2f);
    p = fmaf(p, f, 2.4022651e-1f);
    p = fmaf(p, f, 6.9314718e-1f);
    p = fmaf(p, f, 1.0f);
    return __int_as_float(__float_as_int(p) + (i << 23));
}
#define LOG2E 1.4426950408889634f

// -------- single-launch weight conversion ---------------------------------
#define N4_WA 786432
#define N4_WP 262144
#define N4_WF 1048576
#define N4_W2 1048576
#define N4_TOT (N4_WA + N4_WP + N4_WF + N4_W2)

__global__ __launch_bounds__(256) void conv_all(
    const float* __restrict__ wa, const float* __restrict__ wp,
    const float* __restrict__ wf, const float* __restrict__ w2)
{
    int i = blockIdx.x * 256 + threadIdx.x;
    if (i >= N4_TOT) return;
    const float* src;
    __half *hi, *ls;
    int j = i;
    if (j < N4_WA) {
        src = wa; hi = g_wa_h; ls = g_wa_l;
    } else if ((j -= N4_WA) < N4_WP) {
        src = wp; hi = g_wp_h; ls = g_wp_l;
    } else if ((j -= N4_WP) < N4_WF) {
        src = wf; hi = g_wf_h; ls = g_wf_l;
    } else {
        j -= N4_WF;
        src = w2; hi = g_w2_h; ls = g_w2_l;
    }
    float4 v = ((const float4*)src)[j];
    ((uint2*)hi)[j] = make_uint2(pack_h(v.x, v.y),  pack_h(v.z, v.w));
    ((uint2*)ls)[j] = make_uint2(pack_ls(v.x, v.y), pack_ls(v.z, v.w));
}

// =========================================================================
// 2-term split-fp16 GEMM, BK=64 chunks, 2-stage ring, one sync per chunk,
// 2 CTAs/SM (104 KB smem/CTA).  (unchanged from R12 — passing at 763.5)
// =========================================================================
#define A_STRIDE 144
#define B_STRIDE 272
#define SZ_A (128 * A_STRIDE)          // 18432
#define SZ_B (64 * B_STRIDE)           // 17408
#define OFF_B  SZ_A
#define STAGE_BYTES (SZ_A + 2 * SZ_B)  // 53248
#define GEMM_SMEM (2 * STAGE_BYTES)    // 106496

template<int EPI>
__global__ __launch_bounds__(256, 2) void mma_gemm(
    const __half* __restrict__ A,
    const __half* __restrict__ Wh, const __half* __restrict__ Wls,
    const float* __restrict__ bias, const float* __restrict__ res,
    float* __restrict__ outf, __half* __restrict__ outh,
    __half* __restrict__ q_, __half* __restrict__ kh_, __half* __restrict__ kls_,
    __half* __restrict__ vh_, __half* __restrict__ vls_,
    int M, int N, int K)
{
    extern __shared__ char smem_raw[];
    const uint32_t sm = smem_u32(smem_raw);

    const int tid  = threadIdx.x;
    const int wid  = tid >> 5;
    const int lane = tid & 31;
    const int bm   = blockIdx.y * 128;
    const int bn   = blockIdx.x * 128;
    const int wm   = wid >> 2;
    const int wn   = wid & 3;
    const int nch  = K >> 6;

    float acc[4][4][4];
    #pragma unroll
    for (int i = 0; i < 4; i++)
        #pragma unroll
        for (int j = 0; j < 4; j++)
            #pragma unroll
            for (int q = 0; q < 4; q++) acc[i][j][q] = 0.f;

    auto load_stage = [&](int c) {
        if (c < nch) {
            const int s  = c & 1;
            const int k0 = c << 6;
            const uint32_t sb = sm + s * STAGE_BYTES;
            #pragma unroll
            for (int u = 0; u < 4; u++) {
                int f   = u * 256 + tid;
                int row = f >> 3, seg = f & 7;
                cp16(sb + row * A_STRIDE + seg * 16,
                     A + (size_t)(bm + row) * K + k0 + seg * 8);
            }
            #pragma unroll
            for (int j = 0; j < 2; j++) {
                const __half* src = (j == 0) ? Wh : Wls;
                #pragma unroll
                for (int u = 0; u < 4; u++) {
                    int i  = u * 256 + tid;
                    int kr = i >> 4, seg = i & 15;
                    cp16(sb + OFF_B + j * SZ_B + kr * B_STRIDE + seg * 16,
                         src + (size_t)(k0 + kr) * N + bn + seg * 8);
                }
            }
        }
        CP_COMMIT();
    };

    load_stage(0);

    const int lr = lane & 15;
    const int lc = lane >> 4;

    for (int c = 0; c < nch; c++) {
        CP_WAIT0();
        __syncthreads();
        load_stage(c + 1);

        const uint32_t sb = sm + (c & 1) * STAGE_BYTES;

        #pragma unroll
        for (int ks = 0; ks < 4; ks++) {
            uint32_t ah[4][4], as[4][4];
            #pragma unroll
            for (int mf = 0; mf < 4; mf++) {
                uint32_t ao = sb + (wm * 64 + mf * 16 + lr) * A_STRIDE
                            + lc * 16 + ks * 32;
                ldsm4(ah[mf], ao);
                #pragma unroll
                for (int r = 0; r < 4; r++) as[mf][r] = hscale(ah[mf][r]);
            }
            #pragma unroll
            for (int nt = 0; nt < 2; nt++) {
                uint32_t bh4[4], bl4[4];
                uint32_t bo = sb + OFF_B + (ks * 16 + lr) * B_STRIDE
                            + (wn * 32 + nt * 16 + lc * 8) * 2;
                ldsm4t(bh4, bo);
                ldsm4t(bl4, bo + SZ_B);
                #pragma unroll
                for (int mf = 0; mf < 4; mf++) {
                    mma_f16(acc[mf][nt*2],   ah[mf], bh4[0], bh4[1]);
                    mma_f16(acc[mf][nt*2],   as[mf], bl4[0], bl4[1]);
                    mma_f16(acc[mf][nt*2+1], ah[mf], bh4[2], bh4[3]);
                    mma_f16(acc[mf][nt*2+1], as[mf], bl4[2], bl4[3]);
                }
            }
        }
    }

    // ---- epilogue ----
    #pragma unroll
    for (int mf = 0; mf < 4; mf++) {
        #pragma unroll
        for (int nf = 0; nf < 4; nf++) {
            int col = bn + wn * 32 + nf * 8 + (lane & 3) * 2;
            float2 bv = *(const float2*)(bias + col);
            #pragma unroll
            for (int half = 0; half < 2; half++) {
                int row = bm + wm * 64 + mf * 16 + (lane >> 2) + half * 8;
                float v0 = acc[mf][nf][half * 2 + 0] + bv.x;
                float v1 = acc[mf][nf][half * 2 + 1] + bv.y;
                if (EPI == 1) {
                    v0 = gelu_f(v0); v1 = gelu_f(v1);
                    *(uint32_t*)(outh + (size_t)row * N + col) = pack_h(v0, v1);
                } else if (EPI == 3) {
                    int sector = col >> 10;
                    int wcol = col & 1023;
                    int hh = wcol >> 6;
                    int dd = wcol & 63;
                    int brow = row >> 11;
                    int lrow = row & 2047;
                    size_t dst = ((size_t)(brow * Hx + hh) * Lx + lrow) * Dx + dd;
                    if (sector == 0) {
                        *(uint32_t*)(q_ + dst) = pack_h(v0 * 0.125f, v1 * 0.125f);
                    } else if (sector == 1) {
                        *(uint32_t*)(kh_  + dst) = pack_h(v0, v1);
                        *(uint32_t*)(kls_ + dst) = pack_ls(v0, v1);
                    } else {
                        *(uint32_t*)(vh_  + dst) = pack_h(v0, v1);
                        *(uint32_t*)(vls_ + dst) = pack_ls(v0, v1);
                    }
                } else {
                    float2 rv = *(const float2*)(res + (size_t)row * N + col);
                    v0 += rv.x; v1 += rv.y;
                    *(float2*)(outf + (size_t)row * N + col) = make_float2(v0, v1);
                }
            }
        }
    }
}

// ---------------- LayerNorm -> fp16 output --------------------------------
__global__ __launch_bounds__(256) void ln_kernel(const float* __restrict__ x,
                                                 const float* __restrict__ w,
                                                 const float* __restrict__ b,
                                                 __half* __restrict__ oh)
{
    int row = blockIdx.x;
    int t   = threadIdx.x;
    const float4* xr = (const float4*)(x + (size_t)row * Cx);
    float4 v = xr[t];
    float s  = v.x + v.y + v.z + v.w;
    float sq = v.x*v.x + v.y*v.y + v.z*v.z + v.w*v.w;
    #pragma unroll
    for (int o = 16; o > 0; o >>= 1) {
        s  += __shfl_xor_sync(0xffffffffu, s,  o);
        sq += __shfl_xor_sync(0xffffffffu, sq, o);
    }
    __shared__ float ss[8], ssq[8];
    int wid = t >> 5, lane = t & 31;
    if (lane == 0) { ss[wid] = s; ssq[wid] = sq; }
    __syncthreads();
    float tot = 0.f, totq = 0.f;
    #pragma unroll
    for (int i = 0; i < 8; i++) { tot += ss[i]; totq += ssq[i]; }
    float mean = tot * (1.0f / Cx);
    float var  = totq * (1.0f / Cx) - mean * mean;
    float rstd = rsqrtf(var + 1e-5f);
    const float4 wv = ((const float4*)w)[t];
    const float4 bv = ((const float4*)b)[t];
    float o0 = (v.x - mean) * rstd * wv.x + bv.x;
    float o1 = (v.y - mean) * rstd * wv.y + bv.y;
    float o2 = (v.z - mean) * rstd * wv.z + bv.z;
    float o3 = (v.w - mean) * rstd * wv.w + bv.w;
    size_t idx = (size_t)row * Cx + t * 4;
    *(uint2*)(oh + idx) = make_uint2(pack_h(o0, o1), pack_h(o2, o3));
}

// =========================================================================
// Tensor-core causal flash attention, 2-term split-fp16.
// 128 threads (4 warps), 64 q-rows/CTA, 2-stage KV ring.
// Q parks inside stage-1's smem (kv1 load deferred past a Q-read barrier)
// -> 72 KB smem; scaled fragments recomputed in 4-reg slices -> ~160 regs
// -> 3 CTAs/SM (12 warps).
// =========================================================================
#define QSTR 144
#define ATT_KVS  9216             // one array (64 rows x 144B)
#define ATT_STG  (4*ATT_KVS)      // 36864
#define ATT_SMEM (2*ATT_STG)      // 73728 -> 3 CTAs/SM

__global__ __launch_bounds__(128, 3) void attn_mma(
    const __half* __restrict__ q_,
    const __half* __restrict__ kh_, const __half* __restrict__ kls_,
    const __half* __restrict__ vh_, const __half* __restrict__ vls_,
    __half* __restrict__ y_)
{
    extern __shared__ char sm_raw[];
    const uint32_t S = smem_u32(sm_raw);
    const int tid = threadIdx.x, wid = tid >> 5, lane = tid & 31;
    const int qt  = gridDim.x - 1 - blockIdx.x;   // heavy CTAs first
    const int qb  = qt * 64;
    const int bh  = blockIdx.y;
    const size_t hb = (size_t)bh * Lx * Dx;

    const __half *Q  = q_  + hb;
    const __half *Kh = kh_ + hb, *Kl = kls_ + hb;
    const __half *Vh = vh_ + hb, *Vl = vls_ + hb;

    const int nk = qt + 1;

    auto load_kv = [&](int kt) {
        if (kt < nk) {
            const uint32_t db = S + (kt & 1) * ATT_STG;
            #pragma unroll
            for (int u = 0; u < 16; u++) {
                int j = u * 128 + tid;
                int arr = j >> 9;
                int rem = j & 511;
                int row = rem >> 3, seg = rem & 7;
                const __half* src = (arr == 0) ? Kh : (arr == 1) ? Kl
                                   : (arr == 2) ? Vh : Vl;
                cp16(db + arr * ATT_KVS + row * QSTR + seg * 16,
                     src + (size_t)(kt * 64 + row) * Dx + seg * 8);
            }
        }
        CP_COMMIT();
    };

    // prologue: Q -> first 9 KB of stage-1 space; kv0 -> stage 0; one group
    const uint32_t QBASE = S + ATT_STG;
    #pragma unroll
    for (int u = 0; u < 4; u++) {
        int j = u * 128 + tid;
        int row = j >> 3, seg = j & 7;
        cp16(QBASE + row * QSTR + seg * 16,
             Q + (size_t)(qb + row) * Dx + seg * 8);
    }
    #pragma unroll
    for (int u = 0; u < 16; u++) {
        int j = u * 128 + tid;
        int arr = j >> 9;
        int rem = j & 511;
        int row = rem >> 3, seg = rem & 7;
        const __half* src = (arr == 0) ? Kh : (arr == 1) ? Kl
                           : (arr == 2) ? Vh : Vl;
        cp16(S + arr * ATT_KVS + row * QSTR + seg * 16,
             src + (size_t)row * Dx + seg * 8);
    }
    CP_COMMIT();
    CP_WAIT0();
    __syncthreads();

    // extract Q fragments, then free the Q region for kv1
    uint32_t qf[4][4];
    #pragma unroll
    for (int ks = 0; ks < 4; ks++) {
        uint32_t ao = QBASE + (wid * 16 + (lane & 15)) * QSTR
                    + (lane >> 4) * 16 + ks * 32;
        ldsm4(qf[ks], ao);
    }
    __syncthreads();             // all warps done reading Q smem

    float oc[8][4];
    #pragma unroll
    for (int d = 0; d < 8; d++)
        #pragma unroll
        for (int i = 0; i < 4; i++) oc[d][i] = 0.f;
    float m0 = -1e30f, m1 = -1e30f, l0 = 0.f, l1 = 0.f;

    const int r0g = qb + wid * 16 + (lane >> 2);

    for (int kt = 0; kt < nk; kt++) {
        if (kt == 0) {
            load_kv(1);          // overwrites Q region (read-barrier passed)
        } else {
            CP_WAIT0();          // kv(kt) arrived
            __syncthreads();     // all warps done with tile kt-1
            load_kv(kt + 1);     // stage (kt+1)&1 reused from kt-1: safe
        }

        const int k0 = kt * 64;
        const uint32_t kb = S + (kt & 1) * ATT_STG;

        // ---- S = Q @ K^T (2-term; scaled-Q slices recomputed) ----
        float sc[8][4];
        #pragma unroll
        for (int nt = 0; nt < 8; nt++)
            #pragma unroll
            for (int i = 0; i < 4; i++) sc[nt][i] = 0.f;

        #pragma unroll
        for (int ks = 0; ks < 4; ks++) {
            uint32_t qsk[4];
            #pragma unroll
            for (int r = 0; r < 4; r++) qsk[r] = hscale(qf[ks][r]);
            uint32_t k4[4][4], kl4[4][4];
            #pragma unroll
            for (int ntp = 0; ntp < 4; ntp++) {
                uint32_t ad = kb
                    + (uint32_t)((ntp * 16 + (lane & 7) + ((lane >> 4) << 3)) * QSTR)
                    + ((lane >> 3) & 1) * 16 + ks * 32;
                ldsm4(k4[ntp], ad);
                ldsm4(kl4[ntp], ad + ATT_KVS);
            }
            #pragma unroll
            for (int ntp = 0; ntp < 4; ntp++)
                #pragma unroll
                for (int hf = 0; hf < 2; hf++) {
                    int nt = ntp * 2 + hf, p = hf * 2;
                    mma_f16(sc[nt], qf[ks], k4[ntp][p],  k4[ntp][p + 1]);
                    mma_f16(sc[nt], qsk,    kl4[ntp][p], kl4[ntp][p + 1]);
                }
        }

        // ---- causal mask (diagonal tile only) ----
        if (kt == qt) {
            #pragma unroll
            for (int nt = 0; nt < 8; nt++) {
                int key = k0 + nt * 8 + (lane & 3) * 2;
                if (key     > r0g)     sc[nt][0] = -1e30f;
                if (key + 1 > r0g)     sc[nt][1] = -1e30f;
                if (key     > r0g + 8) sc[nt][2] = -1e30f;
                if (key + 1 > r0g + 8) sc[nt][3] = -1e30f;
            }
        }

        // ---- online softmax ----
        float rm0 = -1e30f, rm1 = -1e30f;
        #pragma unroll
        for (int nt = 0; nt < 8; nt++) {
            rm0 = fmaxf(rm0, fmaxf(sc[nt][0], sc[nt][1]));
            rm1 = fmaxf(rm1, fmaxf(sc[nt][2], sc[nt][3]));
        }
        rm0 = fmaxf(rm0, __shfl_xor_sync(0xffffffffu, rm0, 1));
        rm0 = fmaxf(rm0, __shfl_xor_sync(0xffffffffu, rm0, 2));
        rm1 = fmaxf(rm1, __shfl_xor_sync(0xffffffffu, rm1, 1));
        rm1 = fmaxf(rm1, __shfl_xor_sync(0xffffffffu, rm1, 2));
        float mn0 = fmaxf(m0, rm0 * LOG2E);
        float mn1 = fmaxf(m1, rm1 * LOG2E);
        float s0 = pexp2(m0 - mn0);
        float s1 = pexp2(m1 - mn1);
        m0 = mn0; m1 = mn1;
        l0 *= s0; l1 *= s1;
        #pragma unroll
        for (int d = 0; d < 8; d++) {
            oc[d][0] *= s0; oc[d][1] *= s0;
            oc[d][2] *= s1; oc[d][3] *= s1;
        }

        uint32_t pa[4][4];
        float la0 = 0.f, la1 = 0.f;
        #pragma unroll
        for (int nt = 0; nt < 8; nt++) {
            float p0 = pexp2(fmaf(sc[nt][0], LOG2E, -m0));
            float p1 = pexp2(fmaf(sc[nt][1], LOG2E, -m0));
            float p2 = pexp2(fmaf(sc[nt][2], LOG2E, -m1));
            float p3 = pexp2(fmaf(sc[nt][3], LOG2E, -m1));
            la0 += p0 + p1;
            la1 += p2 + p3;
            int ks2 = nt >> 1, idx = (nt & 1) * 2;
            pa[ks2][idx]     = pack_h(p0, p1);
            pa[ks2][idx + 1] = pack_h(p2, p3);
        }
        l0 += la0; l1 += la1;

        // ---- O += P @ V (2-term; scaled-P slices recomputed) ----
        #pragma unroll
        for (int ks2 = 0; ks2 < 4; ks2++) {
            uint32_t pask[4];
            #pragma unroll
            for (int r = 0; r < 4; r++) pask[r] = hscale(pa[ks2][r]);
            uint32_t v4[4][4], vl4[4][4];
            #pragma unroll
            for (int dtp = 0; dtp < 4; dtp++) {
                uint32_t ad = kb + 2 * ATT_KVS
                    + (uint32_t)((ks2 * 16 + (lane & 15)) * QSTR)
                    + (dtp * 16 + (lane >> 4) * 8) * 2;
                ldsm4t(v4[dtp], ad);
                ldsm4t(vl4[dtp], ad + ATT_KVS);
            }
            #pragma unroll
            for (int dtp = 0; dtp < 4; dtp++)
                #pragma unroll
                for (int hf = 0; hf < 2; hf++) {
                    int dt = dtp * 2 + hf, p = hf * 2;
                    mma_f16(oc[dt], pa[ks2], v4[dtp][p],  v4[dtp][p + 1]);
                    mma_f16(oc[dt], pask,    vl4[dtp][p], vl4[dtp][p + 1]);
                }
        }
    }

    // ---- finalize ----
    l0 += __shfl_xor_sync(0xffffffffu, l0, 1);
    l0 += __shfl_xor_sync(0xffffffffu, l0, 2);
    l1 += __shfl_xor_sync(0xffffffffu, l1, 1);
    l1 += __shfl_xor_sync(0xffffffffu, l1, 2);
    float i0 = 1.f / l0, i1 = 1.f / l1;

    const int b  = bh >> 4;
    const int hh = bh & 15;
    const size_t row0 = (size_t)b * Lx + qb + wid * 16 + (lane >> 2);
    const int colb = hh * 64 + (lane & 3) * 2;
    #pragma unroll
    for (int dt = 0; dt < 8; dt++) {
        float a0 = oc[dt][0] * i0, a1 = oc[dt][1] * i0;
        float a2 = oc[dt][2] * i1, a3 = oc[dt][3] * i1;
        *(uint32_t*)(y_ + row0 * Cx + colb + dt * 8)       = pack_h(a0, a1);
        *(uint32_t*)(y_ + (row0 + 8) * Cx + colb + dt * 8) = pack_h(a2, a3);
    }
}

// ---------------- launcher ----------------
extern "C" void kernel_launch(void* const* d_in, const int* in_sizes, int n_in,
                              void* d_out, int out_size)
{
    const float* x      = (const float*)d_in[0];
    const float* ln1_w  = (const float*)d_in[1];
    const float* ln1_b  = (const float*)d_in[2];
    const float* w_attn = (const float*)d_in[3];
    const float* b_attn = (const float*)d_in[4];
    const float* w_proj = (const float*)d_in[5];
    const float* b_proj = (const float*)d_in[6];
    const float* ln2_w  = (const float*)d_in[7];
    const float* ln2_b  = (const float*)d_in[8];
    const float* w_fc   = (const float*)d_in[9];
    const float* b_fc   = (const float*)d_in[10];
    const float* w_fc2  = (const float*)d_in[11];
    const float* b_fc2  = (const float*)d_in[12];
    float* out = (float*)d_out;

    void *px1, *ph, *py, *pfc, *pq, *pkh, *pkl, *pvh, *pvl;
    void *pwah, *pwal, *pwph, *pwpl, *pwfh, *pwfl, *pw2h, *pw2l;
    cudaGetSymbolAddress(&px1, g_x1);
    cudaGetSymbolAddress(&ph,  g_h);
    cudaGetSymbolAddress(&py,  g_y);
    cudaGetSymbolAddress(&pfc, g_fc);
    cudaGetSymbolAddress(&pq,  g_q);
    cudaGetSymbolAddress(&pkh, g_kh);  cudaGetSymbolAddress(&pkl, g_kls);
    cudaGetSymbolAddress(&pvh, g_vh);  cudaGetSymbolAddress(&pvl, g_vls);
    cudaGetSymbolAddress(&pwah, g_wa_h); cudaGetSymbolAddress(&pwal, g_wa_l);
    cudaGetSymbolAddress(&pwph, g_wp_h); cudaGetSymbolAddress(&pwpl, g_wp_l);
    cudaGetSymbolAddress(&pwfh, g_wf_h); cudaGetSymbolAddress(&pwfl, g_wf_l);
    cudaGetSymbolAddress(&pw2h, g_w2_h); cudaGetSymbolAddress(&pw2l, g_w2_l);

    float* x1 = (float*)px1;
    __half* h  = (__half*)ph;
    __half* y  = (__half*)py;
    __half* fc = (__half*)pfc;
    __half* q  = (__half*)pq;
    __half *kh = (__half*)pkh, *kl = (__half*)pkl;
    __half *vh = (__half*)pvh, *vl = (__half*)pvl;
    __half *wah = (__half*)pwah, *wal = (__half*)pwal;
    __half *wph = (__half*)pwph, *wpl = (__half*)pwpl;
    __half *wfh = (__half*)pwfh, *wfl = (__half*)pwfl;
    __half *w2h = (__half*)pw2h, *w2l = (__half*)pw2l;

    static bool attr_done = false;
    if (!attr_done) {
        cudaFuncSetAttribute(mma_gemm<1>, cudaFuncAttributeMaxDynamicSharedMemorySize, GEMM_SMEM);
        cudaFuncSetAttribute(mma_gemm<2>, cudaFuncAttributeMaxDynamicSharedMemorySize, GEMM_SMEM);
        cudaFuncSetAttribute(mma_gemm<3>, cudaFuncAttributeMaxDynamicSharedMemorySize, GEMM_SMEM);
        cudaFuncSetAttribute(attn_mma,    cudaFuncAttributeMaxDynamicSharedMemorySize, ATT_SMEM);
        attr_done = true;
    }

    // 0) weight pre-conversion
    conv_all<<<(N4_TOT + 255)/256, 256>>>(w_attn, w_proj, w_fc, w_fc2);

    // 1) h = LN1(x)
    ln_kernel<<<Mrows, 256>>>(x, ln1_w, ln1_b, h);
    // 2) QKV GEMM -> q (fp16, x0.125) / k,v (hi+ls), [B,H,L,D]
    mma_gemm<3><<<dim3(3*Cx/128, Mrows/128), 256, GEMM_SMEM>>>(
        h, wah, wal, b_attn, nullptr, nullptr, nullptr,
        q, kh, kl, vh, vl, Mrows, 3*Cx, Cx);
    // 3) y = causal flash attention (3 CTAs/SM)
    attn_mma<<<dim3(Lx/64, Bsz*Hx), 128, ATT_SMEM>>>(q, kh, kl, vh, vl, y);
    // 4) x1 = x + y @ w_proj + b_proj
    mma_gemm<2><<<dim3(Cx/128, Mrows/128), 256, GEMM_SMEM>>>(
        y, wph, wpl, b_proj, x, x1, nullptr,
        nullptr, nullptr, nullptr, nullptr, nullptr, Mrows, Cx, Cx);
    // 5) h = LN2(x1)
    ln_kernel<<<Mrows, 256>>>(x1, ln2_w, ln2_b, h);
    // 6) fc = gelu(h @ w_fc + b_fc) -> fp16
    mma_gemm<1><<<dim3(4*Cx/128, Mrows/128), 256, GEMM_SMEM>>>(
        h, wfh, wfl, b_fc, nullptr, nullptr, fc,
        nullptr, nullptr, nullptr, nullptr, nullptr, Mrows, 4*Cx, Cx);
    // 7) out = x1 + fc @ w_fc2 + b_fc2
    mma_gemm<2><<<dim3(Cx/128, Mrows/128), 256, GEMM_SMEM>>>(
        fc, w2h, w2l, b_fc2, x1, out, nullptr,
        nullptr, nullptr, nullptr, nullptr, nullptr, Mrows, Cx, 4*Cx);
}

// round 14
// speedup vs baseline: 1.0887x; 1.0887x over previous
#include <cuda_runtime.h>
#include <cuda_fp16.h>
#include <math.h>
#include <stdint.h>

// Problem constants
#define Bsz 2
#define Lx  2048
#define Cx  1024
#define Hx  16
#define Dx  64
#define Mrows (Bsz*Lx)      // 4096

// ---------------- scratch (__device__ globals: alloc-free) ----------------
__device__ float g_x1 [Mrows * Cx];

__device__ __half g_h  [Mrows * Cx];
__device__ __half g_y  [Mrows * Cx];
__device__ __half g_fc [Mrows * 4 * Cx];

// attention operands, [B,H,L,D] (single fp16)
__device__ __half g_q  [Mrows * Cx];
__device__ __half g_kh [Mrows * Cx];
__device__ __half g_vh [Mrows * Cx];

// weights: hi + scaled lo
__device__ __half g_wa_h [Cx * 3 * Cx];
__device__ __half g_wa_l [Cx * 3 * Cx];
__device__ __half g_wp_h [Cx * Cx];
__device__ __half g_wp_l [Cx * Cx];
__device__ __half g_wf_h [Cx * 4 * Cx];
__device__ __half g_wf_l [Cx * 4 * Cx];
__device__ __half g_w2_h [4 * Cx * Cx];
__device__ __half g_w2_l [4 * Cx * Cx];

// ================= helpers ==========================
__device__ __forceinline__ uint32_t smem_u32(const void* p) {
    uint32_t a;
    asm("{ .reg .u64 t; cvta.to.shared.u64 t, %1; cvt.u32.u64 %0, t; }"
        : "=r"(a) : "l"(p));
    return a;
}
__device__ __forceinline__ uint32_t pack_h(float a, float b) {
    __half2 h = __floats2half2_rn(a, b);
    return *(uint32_t*)&h;
}
__device__ __forceinline__ uint32_t pack_ls(float a, float b) {
    float ha = __half2float(__float2half_rn(a));
    float hb = __half2float(__float2half_rn(b));
    __half2 h = __floats2half2_rn((a - ha) * 2048.f, (b - hb) * 2048.f);
    return *(uint32_t*)&h;
}
__device__ __forceinline__ uint32_t hscale(uint32_t x) {
    uint32_t r;
    asm("mul.rn.f16x2 %0, %1, %2;" : "=r"(r) : "r"(x), "r"(0x10001000u));
    return r;
}

__device__ __forceinline__ void cp16(uint32_t dst, const void* src) {
    asm volatile("cp.async.cg.shared.global [%0], [%1], 16;"
                 :: "r"(dst), "l"(src));
}
#define CP_COMMIT() asm volatile("cp.async.commit_group;" ::: "memory")
#define CP_WAIT0()  asm volatile("cp.async.wait_group 0;" ::: "memory")

__device__ __forceinline__ void ldsm4(uint32_t (&r)[4], uint32_t addr) {
    asm volatile("ldmatrix.sync.aligned.m8n8.x4.shared.b16 {%0,%1,%2,%3}, [%4];"
                 : "=r"(r[0]), "=r"(r[1]), "=r"(r[2]), "=r"(r[3]) : "r"(addr));
}
__device__ __forceinline__ void ldsm4t(uint32_t (&r)[4], uint32_t addr) {
    asm volatile("ldmatrix.sync.aligned.m8n8.x4.trans.shared.b16 {%0,%1,%2,%3}, [%4];"
                 : "=r"(r[0]), "=r"(r[1]), "=r"(r[2]), "=r"(r[3]) : "r"(addr));
}
__device__ __forceinline__ void mma_f16(float (&c)[4], const uint32_t (&a)[4],
                                        uint32_t b0, uint32_t b1) {
    asm volatile(
        "mma.sync.aligned.m16n8k16.row.col.f32.f16.f16.f32 "
        "{%0,%1,%2,%3},{%4,%5,%6,%7},{%8,%9},{%0,%1,%2,%3};"
        : "+f"(c[0]), "+f"(c[1]), "+f"(c[2]), "+f"(c[3])
        : "r"(a[0]), "r"(a[1]), "r"(a[2]), "r"(a[3]), "r"(b0), "r"(b1));
}

__device__ __forceinline__ float gelu_f(float x) {
    float x3 = x * x * x;
    float t  = tanhf(0.7978845608028654f * (x + 0.044715f * x3));
    return 0.5f * x * (1.0f + t);
}

// exp2 on the FMA pipe
__device__ __forceinline__ float pexp2(float t) {
    t = fmaxf(t, -126.f);
    float k  = t + 12582912.f;
    int   i  = __float_as_int(k) - 0x4B400000;
    float fi = k - 12582912.f;
    float f  = t - fi;
    float p  = 1.3333558e-3f;
    p = fmaf(p, f, 9.6181291e-3f);
    p = fmaf(p, f, 5.5504109e-2f);
    p = fmaf(p, f, 2.4022651e-1f);
    p = fmaf(p, f, 6.9314718e-1f);
    p = fmaf(p, f, 1.0f);
    return __int_as_float(__float_as_int(p) + (i << 23));
}
#define LOG2E 1.4426950408889634f

// -------- single-launch weight conversion ---------------------------------
#define N4_WA 786432
#define N4_WP 262144
#define N4_WF 1048576
#define N4_W2 1048576
#define N4_TOT (N4_WA + N4_WP + N4_WF + N4_W2)

__global__ __launch_bounds__(256) void conv_all(
    const float* __restrict__ wa, const float* __restrict__ wp,
    const float* __restrict__ wf, const float* __restrict__ w2)
{
    int i = blockIdx.x * 256 + threadIdx.x;
    if (i >= N4_TOT) return;
    const float* src;
    __half *hi, *ls;
    int j = i;
    if (j < N4_WA) {
        src = wa; hi = g_wa_h; ls = g_wa_l;
    } else if ((j -= N4_WA) < N4_WP) {
        src = wp; hi = g_wp_h; ls = g_wp_l;
    } else if ((j -= N4_WP) < N4_WF) {
        src = wf; hi = g_wf_h; ls = g_wf_l;
    } else {
        j -= N4_WF;
        src = w2; hi = g_w2_h; ls = g_w2_l;
    }
    float4 v = ((const float4*)src)[j];
    ((uint2*)hi)[j] = make_uint2(pack_h(v.x, v.y),  pack_h(v.z, v.w));
    ((uint2*)ls)[j] = make_uint2(pack_ls(v.x, v.y), pack_ls(v.z, v.w));
}

// =========================================================================
// 2-term split-fp16 GEMM, BK=64 chunks, 2-stage ring, one sync per chunk,
// 2 CTAs/SM.  (unchanged from R12 — passing at 763.5)
// EPI: 1 = bias+gelu -> fp16; 2 = bias+residual -> fp32
//      3 = bias, split Q(x0.125)/K/V fp16 in [B,H,L,D]
// =========================================================================
#define A_STRIDE 144
#define B_STRIDE 272
#define SZ_A (128 * A_STRIDE)          // 18432
#define SZ_B (64 * B_STRIDE)           // 17408
#define OFF_B  SZ_A
#define STAGE_BYTES (SZ_A + 2 * SZ_B)  // 53248
#define GEMM_SMEM (2 * STAGE_BYTES)    // 106496

template<int EPI>
__global__ __launch_bounds__(256, 2) void mma_gemm(
    const __half* __restrict__ A,
    const __half* __restrict__ Wh, const __half* __restrict__ Wls,
    const float* __restrict__ bias, const float* __restrict__ res,
    float* __restrict__ outf, __half* __restrict__ outh,
    __half* __restrict__ q_, __half* __restrict__ kh_, __half* __restrict__ vh_,
    int M, int N, int K)
{
    extern __shared__ char smem_raw[];
    const uint32_t sm = smem_u32(smem_raw);

    const int tid  = threadIdx.x;
    const int wid  = tid >> 5;
    const int lane = tid & 31;
    const int bm   = blockIdx.y * 128;
    const int bn   = blockIdx.x * 128;
    const int wm   = wid >> 2;
    const int wn   = wid & 3;
    const int nch  = K >> 6;

    float acc[4][4][4];
    #pragma unroll
    for (int i = 0; i < 4; i++)
        #pragma unroll
        for (int j = 0; j < 4; j++)
            #pragma unroll
            for (int q = 0; q < 4; q++) acc[i][j][q] = 0.f;

    auto load_stage = [&](int c) {
        if (c < nch) {
            const int s  = c & 1;
            const int k0 = c << 6;
            const uint32_t sb = sm + s * STAGE_BYTES;
            #pragma unroll
            for (int u = 0; u < 4; u++) {
                int f   = u * 256 + tid;
                int row = f >> 3, seg = f & 7;
                cp16(sb + row * A_STRIDE + seg * 16,
                     A + (size_t)(bm + row) * K + k0 + seg * 8);
            }
            #pragma unroll
            for (int j = 0; j < 2; j++) {
                const __half* src = (j == 0) ? Wh : Wls;
                #pragma unroll
                for (int u = 0; u < 4; u++) {
                    int i  = u * 256 + tid;
                    int kr = i >> 4, seg = i & 15;
                    cp16(sb + OFF_B + j * SZ_B + kr * B_STRIDE + seg * 16,
                         src + (size_t)(k0 + kr) * N + bn + seg * 8);
                }
            }
        }
        CP_COMMIT();
    };

    load_stage(0);

    const int lr = lane & 15;
    const int lc = lane >> 4;

    for (int c = 0; c < nch; c++) {
        CP_WAIT0();
        __syncthreads();
        load_stage(c + 1);

        const uint32_t sb = sm + (c & 1) * STAGE_BYTES;

        #pragma unroll
        for (int ks = 0; ks < 4; ks++) {
            uint32_t ah[4][4], as[4][4];
            #pragma unroll
            for (int mf = 0; mf < 4; mf++) {
                uint32_t ao = sb + (wm * 64 + mf * 16 + lr) * A_STRIDE
                            + lc * 16 + ks * 32;
                ldsm4(ah[mf], ao);
                #pragma unroll
                for (int r = 0; r < 4; r++) as[mf][r] = hscale(ah[mf][r]);
            }
            #pragma unroll
            for (int nt = 0; nt < 2; nt++) {
                uint32_t bh4[4], bl4[4];
                uint32_t bo = sb + OFF_B + (ks * 16 + lr) * B_STRIDE
                            + (wn * 32 + nt * 16 + lc * 8) * 2;
                ldsm4t(bh4, bo);
                ldsm4t(bl4, bo + SZ_B);
                #pragma unroll
                for (int mf = 0; mf < 4; mf++) {
                    mma_f16(acc[mf][nt*2],   ah[mf], bh4[0], bh4[1]);
                    mma_f16(acc[mf][nt*2],   as[mf], bl4[0], bl4[1]);
                    mma_f16(acc[mf][nt*2+1], ah[mf], bh4[2], bh4[3]);
                    mma_f16(acc[mf][nt*2+1], as[mf], bl4[2], bl4[3]);
                }
            }
        }
    }

    // ---- epilogue ----
    #pragma unroll
    for (int mf = 0; mf < 4; mf++) {
        #pragma unroll
        for (int nf = 0; nf < 4; nf++) {
            int col = bn + wn * 32 + nf * 8 + (lane & 3) * 2;
            float2 bv = *(const float2*)(bias + col);
            #pragma unroll
            for (int half = 0; half < 2; half++) {
                int row = bm + wm * 64 + mf * 16 + (lane >> 2) + half * 8;
                float v0 = acc[mf][nf][half * 2 + 0] + bv.x;
                float v1 = acc[mf][nf][half * 2 + 1] + bv.y;
                if (EPI == 1) {
                    v0 = gelu_f(v0); v1 = gelu_f(v1);
                    *(uint32_t*)(outh + (size_t)row * N + col) = pack_h(v0, v1);
                } else if (EPI == 3) {
                    int sector = col >> 10;
                    int wcol = col & 1023;
                    int hh = wcol >> 6;
                    int dd = wcol & 63;
                    int brow = row >> 11;
                    int lrow = row & 2047;
                    size_t dst = ((size_t)(brow * Hx + hh) * Lx + lrow) * Dx + dd;
                    if (sector == 0) {
                        *(uint32_t*)(q_ + dst) = pack_h(v0 * 0.125f, v1 * 0.125f);
                    } else if (sector == 1) {
                        *(uint32_t*)(kh_ + dst) = pack_h(v0, v1);
                    } else {
                        *(uint32_t*)(vh_ + dst) = pack_h(v0, v1);
                    }
                } else {
                    float2 rv = *(const float2*)(res + (size_t)row * N + col);
                    v0 += rv.x; v1 += rv.y;
                    *(float2*)(outf + (size_t)row * N + col) = make_float2(v0, v1);
                }
            }
        }
    }
}

// ---------------- LayerNorm -> fp16 output --------------------------------
__global__ __launch_bounds__(256) void ln_kernel(const float* __restrict__ x,
                                                 const float* __restrict__ w,
                                                 const float* __restrict__ b,
                                                 __half* __restrict__ oh)
{
    int row = blockIdx.x;
    int t   = threadIdx.x;
    const float4* xr = (const float4*)(x + (size_t)row * Cx);
    float4 v = xr[t];
    float s  = v.x + v.y + v.z + v.w;
    float sq = v.x*v.x + v.y*v.y + v.z*v.z + v.w*v.w;
    #pragma unroll
    for (int o = 16; o > 0; o >>= 1) {
        s  += __shfl_xor_sync(0xffffffffu, s,  o);
        sq += __shfl_xor_sync(0xffffffffu, sq, o);
    }
    __shared__ float ss[8], ssq[8];
    int wid = t >> 5, lane = t & 31;
    if (lane == 0) { ss[wid] = s; ssq[wid] = sq; }
    __syncthreads();
    float tot = 0.f, totq = 0.f;
    #pragma unroll
    for (int i = 0; i < 8; i++) { tot += ss[i]; totq += ssq[i]; }
    float mean = tot * (1.0f / Cx);
    float var  = totq * (1.0f / Cx) - mean * mean;
    float rstd = rsqrtf(var + 1e-5f);
    const float4 wv = ((const float4*)w)[t];
    const float4 bv = ((const float4*)b)[t];
    float o0 = (v.x - mean) * rstd * wv.x + bv.x;
    float o1 = (v.y - mean) * rstd * wv.y + bv.y;
    float o2 = (v.z - mean) * rstd * wv.z + bv.z;
    float o3 = (v.w - mean) * rstd * wv.w + bv.w;
    size_t idx = (size_t)row * Cx + t * 4;
    *(uint2*)(oh + idx) = make_uint2(pack_h(o0, o1), pack_h(o2, o3));
}

// =========================================================================
// Tensor-core causal flash attention, pure fp16 QK/PV (crossbar-bound fix).
// 128 threads (4 warps), 64 q-rows/CTA, 2-stage KV ring (K+V only, 18 KB/stage),
// 46 KB smem -> 3 CTAs/SM.
// =========================================================================
#define QSTR 144
#define ATT_QS   9216
#define ATT_KVS  9216
#define ATT_STG  (2*ATT_KVS)           // 18432 (K + V)
#define ATT_SMEM (ATT_QS + 2*ATT_STG)  // 46080

__global__ __launch_bounds__(128, 3) void attn_mma(
    const __half* __restrict__ q_,
    const __half* __restrict__ kh_,
    const __half* __restrict__ vh_,
    __half* __restrict__ y_)
{
    extern __shared__ char sm_raw[];
    const uint32_t S = smem_u32(sm_raw);
    const int tid = threadIdx.x, wid = tid >> 5, lane = tid & 31;
    const int qt  = gridDim.x - 1 - blockIdx.x;   // heavy CTAs first
    const int qb  = qt * 64;
    const int bh  = blockIdx.y;
    const size_t hb = (size_t)bh * Lx * Dx;

    const __half *Q  = q_  + hb;
    const __half *Kh = kh_ + hb;
    const __half *Vh = vh_ + hb;

    const int nk = qt + 1;

    auto load_kv = [&](int kt) {
        if (kt < nk) {
            const uint32_t db = S + ATT_QS + (kt & 1) * ATT_STG;
            #pragma unroll
            for (int u = 0; u < 8; u++) {
                int j = u * 128 + tid;
                int arr = j >> 9;              // 0 = K, 1 = V
                int rem = j & 511;
                int row = rem >> 3, seg = rem & 7;
                const __half* src = (arr == 0) ? Kh : Vh;
                cp16(db + arr * ATT_KVS + row * QSTR + seg * 16,
                     src + (size_t)(kt * 64 + row) * Dx + seg * 8);
            }
        }
        CP_COMMIT();
    };

    // prologue: {Q, kv0} in one group
    #pragma unroll
    for (int u = 0; u < 4; u++) {
        int j = u * 128 + tid;
        int row = j >> 3, seg = j & 7;
        cp16(S + row * QSTR + seg * 16,
             Q + (size_t)(qb + row) * Dx + seg * 8);
    }
    {
        const uint32_t db = S + ATT_QS;
        #pragma unroll
        for (int u = 0; u < 8; u++) {
            int j = u * 128 + tid;
            int arr = j >> 9;
            int rem = j & 511;
            int row = rem >> 3, seg = rem & 7;
            const __half* src = (arr == 0) ? Kh : Vh;
            cp16(db + arr * ATT_KVS + row * QSTR + seg * 16,
                 src + (size_t)row * Dx + seg * 8);
        }
        CP_COMMIT();
    }

    uint32_t qf[4][4];
    float oc[8][4];
    #pragma unroll
    for (int d = 0; d < 8; d++)
        #pragma unroll
        for (int i = 0; i < 4; i++) oc[d][i] = 0.f;
    float m0 = -1e30f, m1 = -1e30f, l0 = 0.f, l1 = 0.f;

    const int r0g = qb + wid * 16 + (lane >> 2);

    for (int kt = 0; kt < nk; kt++) {
        CP_WAIT0();              // kv(kt) arrived
        __syncthreads();         // all warps done with tile kt-1
        if (kt == 0) {
            #pragma unroll
            for (int ks = 0; ks < 4; ks++) {
                uint32_t ao = S + (wid * 16 + (lane & 15)) * QSTR
                            + (lane >> 4) * 16 + ks * 32;
                ldsm4(qf[ks], ao);
            }
        }
        load_kv(kt + 1);         // writes stage (kt+1)&1, reused from kt-1: safe

        const int k0 = kt * 64;
        const uint32_t kb = S + ATT_QS + (kt & 1) * ATT_STG;

        // ---- S = Q @ K^T (fp16) ----
        float sc[8][4];
        #pragma unroll
        for (int nt = 0; nt < 8; nt++)
            #pragma unroll
            for (int i = 0; i < 4; i++) sc[nt][i] = 0.f;

        #pragma unroll
        for (int ks = 0; ks < 4; ks++) {
            uint32_t k4[4][4];
            #pragma unroll
            for (int ntp = 0; ntp < 4; ntp++) {
                uint32_t ad = kb
                    + (uint32_t)((ntp * 16 + (lane & 7) + ((lane >> 4) << 3)) * QSTR)
                    + ((lane >> 3) & 1) * 16 + ks * 32;
                ldsm4(k4[ntp], ad);
            }
            #pragma unroll
            for (int ntp = 0; ntp < 4; ntp++)
                #pragma unroll
                for (int hf = 0; hf < 2; hf++) {
                    int nt = ntp * 2 + hf, p = hf * 2;
                    mma_f16(sc[nt], qf[ks], k4[ntp][p], k4[ntp][p + 1]);
                }
        }

        // ---- causal mask (diagonal tile only) ----
        if (kt == qt) {
            #pragma unroll
            for (int nt = 0; nt < 8; nt++) {
                int key = k0 + nt * 8 + (lane & 3) * 2;
                if (key     > r0g)     sc[nt][0] = -1e30f;
                if (key + 1 > r0g)     sc[nt][1] = -1e30f;
                if (key     > r0g + 8) sc[nt][2] = -1e30f;
                if (key + 1 > r0g + 8) sc[nt][3] = -1e30f;
            }
        }

        // ---- online softmax ----
        float rm0 = -1e30f, rm1 = -1e30f;
        #pragma unroll
        for (int nt = 0; nt < 8; nt++) {
            rm0 = fmaxf(rm0, fmaxf(sc[nt][0], sc[nt][1]));
            rm1 = fmaxf(rm1, fmaxf(sc[nt][2], sc[nt][3]));
        }
        rm0 = fmaxf(rm0, __shfl_xor_sync(0xffffffffu, rm0, 1));
        rm0 = fmaxf(rm0, __shfl_xor_sync(0xffffffffu, rm0, 2));
        rm1 = fmaxf(rm1, __shfl_xor_sync(0xffffffffu, rm1, 1));
        rm1 = fmaxf(rm1, __shfl_xor_sync(0xffffffffu, rm1, 2));
        float mn0 = fmaxf(m0, rm0 * LOG2E);
        float mn1 = fmaxf(m1, rm1 * LOG2E);
        float s0 = pexp2(m0 - mn0);
        float s1 = pexp2(m1 - mn1);
        m0 = mn0; m1 = mn1;
        l0 *= s0; l1 *= s1;
        #pragma unroll
        for (int d = 0; d < 8; d++) {
            oc[d][0] *= s0; oc[d][1] *= s0;
            oc[d][2] *= s1; oc[d][3] *= s1;
        }

        uint32_t pa[4][4];
        float la0 = 0.f, la1 = 0.f;
        #pragma unroll
        for (int nt = 0; nt < 8; nt++) {
            float p0 = pexp2(fmaf(sc[nt][0], LOG2E, -m0));
            float p1 = pexp2(fmaf(sc[nt][1], LOG2E, -m0));
            float p2 = pexp2(fmaf(sc[nt][2], LOG2E, -m1));
            float p3 = pexp2(fmaf(sc[nt][3], LOG2E, -m1));
            la0 += p0 + p1;
            la1 += p2 + p3;
            int ks2 = nt >> 1, idx = (nt & 1) * 2;
            pa[ks2][idx]     = pack_h(p0, p1);
            pa[ks2][idx + 1] = pack_h(p2, p3);
        }
        l0 += la0; l1 += la1;

        // ---- O += P @ V (fp16) ----
        #pragma unroll
        for (int ks2 = 0; ks2 < 4; ks2++) {
            uint32_t v4[4][4];
            #pragma unroll
            for (int dtp = 0; dtp < 4; dtp++) {
                uint32_t ad = kb + ATT_KVS
                    + (uint32_t)((ks2 * 16 + (lane & 15)) * QSTR)
                    + (dtp * 16 + (lane >> 4) * 8) * 2;
                ldsm4t(v4[dtp], ad);
            }
            #pragma unroll
            for (int dtp = 0; dtp < 4; dtp++)
                #pragma unroll
                for (int hf = 0; hf < 2; hf++) {
                    int dt = dtp * 2 + hf, p = hf * 2;
                    mma_f16(oc[dt], pa[ks2], v4[dtp][p], v4[dtp][p + 1]);
                }
        }
    }

    // ---- finalize ----
    l0 += __shfl_xor_sync(0xffffffffu, l0, 1);
    l0 += __shfl_xor_sync(0xffffffffu, l0, 2);
    l1 += __shfl_xor_sync(0xffffffffu, l1, 1);
    l1 += __shfl_xor_sync(0xffffffffu, l1, 2);
    float i0 = 1.f / l0, i1 = 1.f / l1;

    const int b  = bh >> 4;
    const int hh = bh & 15;
    const size_t row0 = (size_t)b * Lx + qb + wid * 16 + (lane >> 2);
    const int colb = hh * 64 + (lane & 3) * 2;
    #pragma unroll
    for (int dt = 0; dt < 8; dt++) {
        float a0 = oc[dt][0] * i0, a1 = oc[dt][1] * i0;
        float a2 = oc[dt][2] * i1, a3 = oc[dt][3] * i1;
        *(uint32_t*)(y_ + row0 * Cx + colb + dt * 8)       = pack_h(a0, a1);
        *(uint32_t*)(y_ + (row0 + 8) * Cx + colb + dt * 8) = pack_h(a2, a3);
    }
}

// ---------------- launcher ----------------
extern "C" void kernel_launch(void* const* d_in, const int* in_sizes, int n_in,
                              void* d_out, int out_size)
{
    const float* x      = (const float*)d_in[0];
    const float* ln1_w  = (const float*)d_in[1];
    const float* ln1_b  = (const float*)d_in[2];
    const float* w_attn = (const float*)d_in[3];
    const float* b_attn = (const float*)d_in[4];
    const float* w_proj = (const float*)d_in[5];
    const float* b_proj = (const float*)d_in[6];
    const float* ln2_w  = (const float*)d_in[7];
    const float* ln2_b  = (const float*)d_in[8];
    const float* w_fc   = (const float*)d_in[9];
    const float* b_fc   = (const float*)d_in[10];
    const float* w_fc2  = (const float*)d_in[11];
    const float* b_fc2  = (const float*)d_in[12];
    float* out = (float*)d_out;

    void *px1, *ph, *py, *pfc, *pq, *pkh, *pvh;
    void *pwah, *pwal, *pwph, *pwpl, *pwfh, *pwfl, *pw2h, *pw2l;
    cudaGetSymbolAddress(&px1, g_x1);
    cudaGetSymbolAddress(&ph,  g_h);
    cudaGetSymbolAddress(&py,  g_y);
    cudaGetSymbolAddress(&pfc, g_fc);
    cudaGetSymbolAddress(&pq,  g_q);
    cudaGetSymbolAddress(&pkh, g_kh);
    cudaGetSymbolAddress(&pvh, g_vh);
    cudaGetSymbolAddress(&pwah, g_wa_h); cudaGetSymbolAddress(&pwal, g_wa_l);
    cudaGetSymbolAddress(&pwph, g_wp_h); cudaGetSymbolAddress(&pwpl, g_wp_l);
    cudaGetSymbolAddress(&pwfh, g_wf_h); cudaGetSymbolAddress(&pwfl, g_wf_l);
    cudaGetSymbolAddress(&pw2h, g_w2_h); cudaGetSymbolAddress(&pw2l, g_w2_l);

    float* x1 = (float*)px1;
    __half* h  = (__half*)ph;
    __half* y  = (__half*)py;
    __half* fc = (__half*)pfc;
    __half* q  = (__half*)pq;
    __half* kh = (__half*)pkh;
    __half* vh = (__half*)pvh;
    __half *wah = (__half*)pwah, *wal = (__half*)pwal;
    __half *wph = (__half*)pwph, *wpl = (__half*)pwpl;
    __half *wfh = (__half*)pwfh, *wfl = (__half*)pwfl;
    __half *w2h = (__half*)pw2h, *w2l = (__half*)pw2l;

    static bool attr_done = false;
    if (!attr_done) {
        cudaFuncSetAttribute(mma_gemm<1>, cudaFuncAttributeMaxDynamicSharedMemorySize, GEMM_SMEM);
        cudaFuncSetAttribute(mma_gemm<2>, cudaFuncAttributeMaxDynamicSharedMemorySize, GEMM_SMEM);
        cudaFuncSetAttribute(mma_gemm<3>, cudaFuncAttributeMaxDynamicSharedMemorySize, GEMM_SMEM);
        cudaFuncSetAttribute(attn_mma,    cudaFuncAttributeMaxDynamicSharedMemorySize, ATT_SMEM);
        attr_done = true;
    }

    // 0) weight pre-conversion
    conv_all<<<(N4_TOT + 255)/256, 256>>>(w_attn, w_proj, w_fc, w_fc2);

    // 1) h = LN1(x)
    ln_kernel<<<Mrows, 256>>>(x, ln1_w, ln1_b, h);
    // 2) QKV GEMM -> q (fp16, x0.125) / k / v, [B,H,L,D]
    mma_gemm<3><<<dim3(3*Cx/128, Mrows/128), 256, GEMM_SMEM>>>(
        h, wah, wal, b_attn, nullptr, nullptr, nullptr,
        q, kh, vh, Mrows, 3*Cx, Cx);
    // 3) y = causal flash attention (fp16, 3 CTAs/SM)
    attn_mma<<<dim3(Lx/64, Bsz*Hx), 128, ATT_SMEM>>>(q, kh, vh, y);
    // 4) x1 = x + y @ w_proj + b_proj
    mma_gemm<2><<<dim3(Cx/128, Mrows/128), 256, GEMM_SMEM>>>(
        y, wph, wpl, b_proj, x, x1, nullptr,
        nullptr, nullptr, nullptr, Mrows, Cx, Cx);
    // 5) h = LN2(x1)
    ln_kernel<<<Mrows, 256>>>(x1, ln2_w, ln2_b, h);
    // 6) fc = gelu(h @ w_fc + b_fc) -> fp16
    mma_gemm<1><<<dim3(4*Cx/128, Mrows/128), 256, GEMM_SMEM>>>(
        h, wfh, wfl, b_fc, nullptr, nullptr, fc,
        nullptr, nullptr, nullptr, Mrows, 4*Cx, Cx);
    // 7) out = x1 + fc @ w_fc2 + b_fc2
    mma_gemm<2><<<dim3(Cx/128, Mrows/128), 256, GEMM_SMEM>>>(
        fc, w2h, w2l, b_fc2, x1, out, nullptr,
        nullptr, nullptr, nullptr, Mrows, Cx, 4*Cx);
}

// round 15
// speedup vs baseline: 1.6406x; 1.5070x over previous
#include <cuda_runtime.h>
#include <cuda_fp16.h>
#include <math.h>
#include <stdint.h>

// Problem constants
#define Bsz 2
#define Lx  2048
#define Cx  1024
#define Hx  16
#define Dx  64
#define Mrows (Bsz*Lx)      // 4096

// ---------------- scratch (__device__ globals: alloc-free) ----------------
__device__ float g_x1 [Mrows * Cx];

__device__ __half g_h  [Mrows * Cx];
__device__ __half g_y  [Mrows * Cx];
__device__ __half g_fc [Mrows * 4 * Cx];

// attention operands, [B,H,L,D] (single fp16)
__device__ __half g_q  [Mrows * Cx];
__device__ __half g_kh [Mrows * Cx];
__device__ __half g_vh [Mrows * Cx];

// weights: fp16
__device__ __half g_wa_h [Cx * 3 * Cx];
__device__ __half g_wp_h [Cx * Cx];
__device__ __half g_wf_h [Cx * 4 * Cx];
__device__ __half g_w2_h [4 * Cx * Cx];

// ================= helpers ==========================
__device__ __forceinline__ uint32_t smem_u32(const void* p) {
    uint32_t a;
    asm("{ .reg .u64 t; cvta.to.shared.u64 t, %1; cvt.u32.u64 %0, t; }"
        : "=r"(a) : "l"(p));
    return a;
}
__device__ __forceinline__ uint32_t pack_h(float a, float b) {
    __half2 h = __floats2half2_rn(a, b);
    return *(uint32_t*)&h;
}

__device__ __forceinline__ void cp16(uint32_t dst, const void* src) {
    asm volatile("cp.async.cg.shared.global [%0], [%1], 16;"
                 :: "r"(dst), "l"(src));
}
#define CP_COMMIT() asm volatile("cp.async.commit_group;" ::: "memory")
#define CP_WAIT0()  asm volatile("cp.async.wait_group 0;" ::: "memory")
#define CP_WAIT1()  asm volatile("cp.async.wait_group 1;" ::: "memory")

__device__ __forceinline__ void ldsm4(uint32_t (&r)[4], uint32_t addr) {
    asm volatile("ldmatrix.sync.aligned.m8n8.x4.shared.b16 {%0,%1,%2,%3}, [%4];"
                 : "=r"(r[0]), "=r"(r[1]), "=r"(r[2]), "=r"(r[3]) : "r"(addr));
}
__device__ __forceinline__ void ldsm4t(uint32_t (&r)[4], uint32_t addr) {
    asm volatile("ldmatrix.sync.aligned.m8n8.x4.trans.shared.b16 {%0,%1,%2,%3}, [%4];"
                 : "=r"(r[0]), "=r"(r[1]), "=r"(r[2]), "=r"(r[3]) : "r"(addr));
}
__device__ __forceinline__ void mma_f16(float (&c)[4], const uint32_t (&a)[4],
                                        uint32_t b0, uint32_t b1) {
    asm volatile(
        "mma.sync.aligned.m16n8k16.row.col.f32.f16.f16.f32 "
        "{%0,%1,%2,%3},{%4,%5,%6,%7},{%8,%9},{%0,%1,%2,%3};"
        : "+f"(c[0]), "+f"(c[1]), "+f"(c[2]), "+f"(c[3])
        : "r"(a[0]), "r"(a[1]), "r"(a[2]), "r"(a[3]), "r"(b0), "r"(b1));
}

__device__ __forceinline__ float gelu_f(float x) {
    float x3 = x * x * x;
    float t  = tanhf(0.7978845608028654f * (x + 0.044715f * x3));
    return 0.5f * x * (1.0f + t);
}

// exp2 on the FMA pipe
__device__ __forceinline__ float pexp2(float t) {
    t = fmaxf(t, -126.f);
    float k  = t + 12582912.f;
    int   i  = __float_as_int(k) - 0x4B400000;
    float fi = k - 12582912.f;
    float f  = t - fi;
    float p  = 1.3333558e-3f;
    p = fmaf(p, f, 9.6181291e-3f);
    p = fmaf(p, f, 5.5504109e-2f);
    p = fmaf(p, f, 2.4022651e-1f);
    p = fmaf(p, f, 6.9314718e-1f);
    p = fmaf(p, f, 1.0f);
    return __int_as_float(__float_as_int(p) + (i << 23));
}
#define LOG2E 1.4426950408889634f

// -------- single-launch weight conversion (fp32 -> fp16) ------------------
#define N4_WA 786432
#define N4_WP 262144
#define N4_WF 1048576
#define N4_W2 1048576
#define N4_TOT (N4_WA + N4_WP + N4_WF + N4_W2)

__global__ __launch_bounds__(256) void conv_all(
    const float* __restrict__ wa, const float* __restrict__ wp,
    const float* __restrict__ wf, const float* __restrict__ w2)
{
    int i = blockIdx.x * 256 + threadIdx.x;
    if (i >= N4_TOT) return;
    const float* src;
    __half* hi;
    int j = i;
    if (j < N4_WA) {
        src = wa; hi = g_wa_h;
    } else if ((j -= N4_WA) < N4_WP) {
        src = wp; hi = g_wp_h;
    } else if ((j -= N4_WP) < N4_WF) {
        src = wf; hi = g_wf_h;
    } else {
        j -= N4_WF;
        src = w2; hi = g_w2_h;
    }
    float4 v = ((const float4*)src)[j];
    ((uint2*)hi)[j] = make_uint2(pack_h(v.x, v.y), pack_h(v.z, v.w));
}

// =========================================================================
// Plain fp16 GEMM (fp32 accum), BK=64 chunks, 3-stage ring, one sync/chunk,
// 2 CTAs/SM (105 KB smem/CTA).
// EPI: 1 = bias+gelu -> fp16; 2 = bias+residual -> fp32
//      3 = bias, split Q(x0.125)/K/V fp16 in [B,H,L,D]
// =========================================================================
#define A_STRIDE 144
#define B_STRIDE 272
#define SZ_A (128 * A_STRIDE)          // 18432
#define SZ_B (64 * B_STRIDE)           // 17408
#define OFF_B  SZ_A
#define STAGE_BYTES (SZ_A + SZ_B)      // 35840
#define GEMM_SMEM (3 * STAGE_BYTES)    // 107520

template<int EPI>
__global__ __launch_bounds__(256, 2) void mma_gemm(
    const __half* __restrict__ A,
    const __half* __restrict__ Wh,
    const float* __restrict__ bias, const float* __restrict__ res,
    float* __restrict__ outf, __half* __restrict__ outh,
    __half* __restrict__ q_, __half* __restrict__ kh_, __half* __restrict__ vh_,
    int M, int N, int K)
{
    extern __shared__ char smem_raw[];
    const uint32_t sm = smem_u32(smem_raw);

    const int tid  = threadIdx.x;
    const int wid  = tid >> 5;
    const int lane = tid & 31;
    const int bm   = blockIdx.y * 128;
    const int bn   = blockIdx.x * 128;
    const int wm   = wid >> 2;
    const int wn   = wid & 3;
    const int nch  = K >> 6;

    float acc[4][4][4];
    #pragma unroll
    for (int i = 0; i < 4; i++)
        #pragma unroll
        for (int j = 0; j < 4; j++)
            #pragma unroll
            for (int q = 0; q < 4; q++) acc[i][j][q] = 0.f;

    auto load_stage = [&](int c) {
        if (c < nch) {
            const int s  = c % 3;
            const int k0 = c << 6;
            const uint32_t sb = sm + s * STAGE_BYTES;
            // A: 128 rows x 64 halves = 1024 x 16B segs, 4/thread
            #pragma unroll
            for (int u = 0; u < 4; u++) {
                int f   = u * 256 + tid;
                int row = f >> 3, seg = f & 7;
                cp16(sb + row * A_STRIDE + seg * 16,
                     A + (size_t)(bm + row) * K + k0 + seg * 8);
            }
            // B: 64 k-rows x 128 n = 1024 segs, 4/thread
            #pragma unroll
            for (int u = 0; u < 4; u++) {
                int i  = u * 256 + tid;
                int kr = i >> 4, seg = i & 15;
                cp16(sb + OFF_B + kr * B_STRIDE + seg * 16,
                     Wh + (size_t)(k0 + kr) * N + bn + seg * 8);
            }
        }
        CP_COMMIT();
    };

    load_stage(0);
    load_stage(1);

    const int lr = lane & 15;
    const int lc = lane >> 4;

    for (int c = 0; c < nch; c++) {
        CP_WAIT1();              // stage c landed (c+1 may be pending)
        __syncthreads();         // all warps done with compute(c-1)
        load_stage(c + 2);       // writes (c+2)%3 == (c-1)%3: safe after sync

        const uint32_t sb = sm + (c % 3) * STAGE_BYTES;

        #pragma unroll
        for (int ks = 0; ks < 4; ks++) {
            uint32_t ah[4][4];
            #pragma unroll
            for (int mf = 0; mf < 4; mf++) {
                uint32_t ao = sb + (wm * 64 + mf * 16 + lr) * A_STRIDE
                            + lc * 16 + ks * 32;
                ldsm4(ah[mf], ao);
            }
            #pragma unroll
            for (int nt = 0; nt < 2; nt++) {
                uint32_t bh4[4];
                uint32_t bo = sb + OFF_B + (ks * 16 + lr) * B_STRIDE
                            + (wn * 32 + nt * 16 + lc * 8) * 2;
                ldsm4t(bh4, bo);
                #pragma unroll
                for (int mf = 0; mf < 4; mf++) {
                    mma_f16(acc[mf][nt*2],   ah[mf], bh4[0], bh4[1]);
                    mma_f16(acc[mf][nt*2+1], ah[mf], bh4[2], bh4[3]);
                }
            }
        }
    }

    // ---- epilogue ----
    #pragma unroll
    for (int mf = 0; mf < 4; mf++) {
        #pragma unroll
        for (int nf = 0; nf < 4; nf++) {
            int col = bn + wn * 32 + nf * 8 + (lane & 3) * 2;
            float2 bv = *(const float2*)(bias + col);
            #pragma unroll
            for (int half = 0; half < 2; half++) {
                int row = bm + wm * 64 + mf * 16 + (lane >> 2) + half * 8;
                float v0 = acc[mf][nf][half * 2 + 0] + bv.x;
                float v1 = acc[mf][nf][half * 2 + 1] + bv.y;
                if (EPI == 1) {
                    v0 = gelu_f(v0); v1 = gelu_f(v1);
                    *(uint32_t*)(outh + (size_t)row * N + col) = pack_h(v0, v1);
                } else if (EPI == 3) {
                    int sector = col >> 10;
                    int wcol = col & 1023;
                    int hh = wcol >> 6;
                    int dd = wcol & 63;
                    int brow = row >> 11;
                    int lrow = row & 2047;
                    size_t dst = ((size_t)(brow * Hx + hh) * Lx + lrow) * Dx + dd;
                    if (sector == 0) {
                        *(uint32_t*)(q_ + dst) = pack_h(v0 * 0.125f, v1 * 0.125f);
                    } else if (sector == 1) {
                        *(uint32_t*)(kh_ + dst) = pack_h(v0, v1);
                    } else {
                        *(uint32_t*)(vh_ + dst) = pack_h(v0, v1);
                    }
                } else {
                    float2 rv = *(const float2*)(res + (size_t)row * N + col);
                    v0 += rv.x; v1 += rv.y;
                    *(float2*)(outf + (size_t)row * N + col) = make_float2(v0, v1);
                }
            }
        }
    }
}

// ---------------- LayerNorm -> fp16 output --------------------------------
__global__ __launch_bounds__(256) void ln_kernel(const float* __restrict__ x,
                                                 const float* __restrict__ w,
                                                 const float* __restrict__ b,
                                                 __half* __restrict__ oh)
{
    int row = blockIdx.x;
    int t   = threadIdx.x;
    const float4* xr = (const float4*)(x + (size_t)row * Cx);
    float4 v = xr[t];
    float s  = v.x + v.y + v.z + v.w;
    float sq = v.x*v.x + v.y*v.y + v.z*v.z + v.w*v.w;
    #pragma unroll
    for (int o = 16; o > 0; o >>= 1) {
        s  += __shfl_xor_sync(0xffffffffu, s,  o);
        sq += __shfl_xor_sync(0xffffffffu, sq, o);
    }
    __shared__ float ss[8], ssq[8];
    int wid = t >> 5, lane = t & 31;
    if (lane == 0) { ss[wid] = s; ssq[wid] = sq; }
    __syncthreads();
    float tot = 0.f, totq = 0.f;
    #pragma unroll
    for (int i = 0; i < 8; i++) { tot += ss[i]; totq += ssq[i]; }
    float mean = tot * (1.0f / Cx);
    float var  = totq * (1.0f / Cx) - mean * mean;
    float rstd = rsqrtf(var + 1e-5f);
    const float4 wv = ((const float4*)w)[t];
    const float4 bv = ((const float4*)b)[t];
    float o0 = (v.x - mean) * rstd * wv.x + bv.x;
    float o1 = (v.y - mean) * rstd * wv.y + bv.y;
    float o2 = (v.z - mean) * rstd * wv.z + bv.z;
    float o3 = (v.w - mean) * rstd * wv.w + bv.w;
    size_t idx = (size_t)row * Cx + t * 4;
    *(uint2*)(oh + idx) = make_uint2(pack_h(o0, o1), pack_h(o2, o3));
}

// =========================================================================
// Tensor-core causal flash attention, pure fp16 (R14 body, passing at 93 us).
// 128 threads (4 warps), 64 q-rows/CTA, 2-stage KV ring, 46 KB smem.
// =========================================================================
#define QSTR 144
#define ATT_QS   9216
#define ATT_KVS  9216
#define ATT_STG  (2*ATT_KVS)           // 18432 (K + V)
#define ATT_SMEM (ATT_QS + 2*ATT_STG)  // 46080

__global__ __launch_bounds__(128, 3) void attn_mma(
    const __half* __restrict__ q_,
    const __half* __restrict__ kh_,
    const __half* __restrict__ vh_,
    __half* __restrict__ y_)
{
    extern __shared__ char sm_raw[];
    const uint32_t S = smem_u32(sm_raw);
    const int tid = threadIdx.x, wid = tid >> 5, lane = tid & 31;
    const int qt  = gridDim.x - 1 - blockIdx.x;   // heavy CTAs first
    const int qb  = qt * 64;
    const int bh  = blockIdx.y;
    const size_t hb = (size_t)bh * Lx * Dx;

    const __half *Q  = q_  + hb;
    const __half *Kh = kh_ + hb;
    const __half *Vh = vh_ + hb;

    const int nk = qt + 1;

    auto load_kv = [&](int kt) {
        if (kt < nk) {
            const uint32_t db = S + ATT_QS + (kt & 1) * ATT_STG;
            #pragma unroll
            for (int u = 0; u < 8; u++) {
                int j = u * 128 + tid;
                int arr = j >> 9;              // 0 = K, 1 = V
                int rem = j & 511;
                int row = rem >> 3, seg = rem & 7;
                const __half* src = (arr == 0) ? Kh : Vh;
                cp16(db + arr * ATT_KVS + row * QSTR + seg * 16,
                     src + (size_t)(kt * 64 + row) * Dx + seg * 8);
            }
        }
        CP_COMMIT();
    };

    // prologue: {Q, kv0} in one group
    #pragma unroll
    for (int u = 0; u < 4; u++) {
        int j = u * 128 + tid;
        int row = j >> 3, seg = j & 7;
        cp16(S + row * QSTR + seg * 16,
             Q + (size_t)(qb + row) * Dx + seg * 8);
    }
    {
        const uint32_t db = S + ATT_QS;
        #pragma unroll
        for (int u = 0; u < 8; u++) {
            int j = u * 128 + tid;
            int arr = j >> 9;
            int rem = j & 511;
            int row = rem >> 3, seg = rem & 7;
            const __half* src = (arr == 0) ? Kh : Vh;
            cp16(db + arr * ATT_KVS + row * QSTR + seg * 16,
                 src + (size_t)row * Dx + seg * 8);
        }
        CP_COMMIT();
    }

    uint32_t qf[4][4];
    float oc[8][4];
    #pragma unroll
    for (int d = 0; d < 8; d++)
        #pragma unroll
        for (int i = 0; i < 4; i++) oc[d][i] = 0.f;
    float m0 = -1e30f, m1 = -1e30f, l0 = 0.f, l1 = 0.f;

    const int r0g = qb + wid * 16 + (lane >> 2);

    for (int kt = 0; kt < nk; kt++) {
        CP_WAIT0();              // kv(kt) arrived
        __syncthreads();         // all warps done with tile kt-1
        if (kt == 0) {
            #pragma unroll
            for (int ks = 0; ks < 4; ks++) {
                uint32_t ao = S + (wid * 16 + (lane & 15)) * QSTR
                            + (lane >> 4) * 16 + ks * 32;
                ldsm4(qf[ks], ao);
            }
        }
        load_kv(kt + 1);         // writes stage (kt+1)&1, reused from kt-1: safe

        const int k0 = kt * 64;
        const uint32_t kb = S + ATT_QS + (kt & 1) * ATT_STG;

        // ---- S = Q @ K^T (fp16) ----
        float sc[8][4];
        #pragma unroll
        for (int nt = 0; nt < 8; nt++)
            #pragma unroll
            for (int i = 0; i < 4; i++) sc[nt][i] = 0.f;

        #pragma unroll
        for (int ks = 0; ks < 4; ks++) {
            uint32_t k4[4][4];
            #pragma unroll
            for (int ntp = 0; ntp < 4; ntp++) {
                uint32_t ad = kb
                    + (uint32_t)((ntp * 16 + (lane & 7) + ((lane >> 4) << 3)) * QSTR)
                    + ((lane >> 3) & 1) * 16 + ks * 32;
                ldsm4(k4[ntp], ad);
            }
            #pragma unroll
            for (int ntp = 0; ntp < 4; ntp++)
                #pragma unroll
                for (int hf = 0; hf < 2; hf++) {
                    int nt = ntp * 2 + hf, p = hf * 2;
                    mma_f16(sc[nt], qf[ks], k4[ntp][p], k4[ntp][p + 1]);
                }
        }

        // ---- causal mask (diagonal tile only) ----
        if (kt == qt) {
            #pragma unroll
            for (int nt = 0; nt < 8; nt++) {
                int key = k0 + nt * 8 + (lane & 3) * 2;
                if (key     > r0g)     sc[nt][0] = -1e30f;
                if (key + 1 > r0g)     sc[nt][1] = -1e30f;
                if (key     > r0g + 8) sc[nt][2] = -1e30f;
                if (key + 1 > r0g + 8) sc[nt][3] = -1e30f;
            }
        }

        // ---- online softmax ----
        float rm0 = -1e30f, rm1 = -1e30f;
        #pragma unroll
        for (int nt = 0; nt < 8; nt++) {
            rm0 = fmaxf(rm0, fmaxf(sc[nt][0], sc[nt][1]));
            rm1 = fmaxf(rm1, fmaxf(sc[nt][2], sc[nt][3]));
        }
        rm0 = fmaxf(rm0, __shfl_xor_sync(0xffffffffu, rm0, 1));
        rm0 = fmaxf(rm0, __shfl_xor_sync(0xffffffffu, rm0, 2));
        rm1 = fmaxf(rm1, __shfl_xor_sync(0xffffffffu, rm1, 1));
        rm1 = fmaxf(rm1, __shfl_xor_sync(0xffffffffu, rm1, 2));
        float mn0 = fmaxf(m0, rm0 * LOG2E);
        float mn1 = fmaxf(m1, rm1 * LOG2E);
        float s0 = pexp2(m0 - mn0);
        float s1 = pexp2(m1 - mn1);
        m0 = mn0; m1 = mn1;
        l0 *= s0; l1 *= s1;
        #pragma unroll
        for (int d = 0; d < 8; d++) {
            oc[d][0] *= s0; oc[d][1] *= s0;
            oc[d][2] *= s1; oc[d][3] *= s1;
        }

        uint32_t pa[4][4];
        float la0 = 0.f, la1 = 0.f;
        #pragma unroll
        for (int nt = 0; nt < 8; nt++) {
            float p0 = pexp2(fmaf(sc[nt][0], LOG2E, -m0));
            float p1 = pexp2(fmaf(sc[nt][1], LOG2E, -m0));
            float p2 = pexp2(fmaf(sc[nt][2], LOG2E, -m1));
            float p3 = pexp2(fmaf(sc[nt][3], LOG2E, -m1));
            la0 += p0 + p1;
            la1 += p2 + p3;
            int ks2 = nt >> 1, idx = (nt & 1) * 2;
            pa[ks2][idx]     = pack_h(p0, p1);
            pa[ks2][idx + 1] = pack_h(p2, p3);
        }
        l0 += la0; l1 += la1;

        // ---- O += P @ V (fp16) ----
        #pragma unroll
        for (int ks2 = 0; ks2 < 4; ks2++) {
            uint32_t v4[4][4];
            #pragma unroll
            for (int dtp = 0; dtp < 4; dtp++) {
                uint32_t ad = kb + ATT_KVS
                    + (uint32_t)((ks2 * 16 + (lane & 15)) * QSTR)
                    + (dtp * 16 + (lane >> 4) * 8) * 2;
                ldsm4t(v4[dtp], ad);
            }
            #pragma unroll
            for (int dtp = 0; dtp < 4; dtp++)
                #pragma unroll
                for (int hf = 0; hf < 2; hf++) {
                    int dt = dtp * 2 + hf, p = hf * 2;
                    mma_f16(oc[dt], pa[ks2], v4[dtp][p], v4[dtp][p + 1]);
                }
        }
    }

    // ---- finalize ----
    l0 += __shfl_xor_sync(0xffffffffu, l0, 1);
    l0 += __shfl_xor_sync(0xffffffffu, l0, 2);
    l1 += __shfl_xor_sync(0xffffffffu, l1, 1);
    l1 += __shfl_xor_sync(0xffffffffu, l1, 2);
    float i0 = 1.f / l0, i1 = 1.f / l1;

    const int b  = bh >> 4;
    const int hh = bh & 15;
    const size_t row0 = (size_t)b * Lx + qb + wid * 16 + (lane >> 2);
    const int colb = hh * 64 + (lane & 3) * 2;
    #pragma unroll
    for (int dt = 0; dt < 8; dt++) {
        float a0 = oc[dt][0] * i0, a1 = oc[dt][1] * i0;
        float a2 = oc[dt][2] * i1, a3 = oc[dt][3] * i1;
        *(uint32_t*)(y_ + row0 * Cx + colb + dt * 8)       = pack_h(a0, a1);
        *(uint32_t*)(y_ + (row0 + 8) * Cx + colb + dt * 8) = pack_h(a2, a3);
    }
}

// ---------------- launcher ----------------
extern "C" void kernel_launch(void* const* d_in, const int* in_sizes, int n_in,
                              void* d_out, int out_size)
{
    const float* x      = (const float*)d_in[0];
    const float* ln1_w  = (const float*)d_in[1];
    const float* ln1_b  = (const float*)d_in[2];
    const float* w_attn = (const float*)d_in[3];
    const float* b_attn = (const float*)d_in[4];
    const float* w_proj = (const float*)d_in[5];
    const float* b_proj = (const float*)d_in[6];
    const float* ln2_w  = (const float*)d_in[7];
    const float* ln2_b  = (const float*)d_in[8];
    const float* w_fc   = (const float*)d_in[9];
    const float* b_fc   = (const float*)d_in[10];
    const float* w_fc2  = (const float*)d_in[11];
    const float* b_fc2  = (const float*)d_in[12];
    float* out = (float*)d_out;

    void *px1, *ph, *py, *pfc, *pq, *pkh, *pvh;
    void *pwah, *pwph, *pwfh, *pw2h;
    cudaGetSymbolAddress(&px1, g_x1);
    cudaGetSymbolAddress(&ph,  g_h);
    cudaGetSymbolAddress(&py,  g_y);
    cudaGetSymbolAddress(&pfc, g_fc);
    cudaGetSymbolAddress(&pq,  g_q);
    cudaGetSymbolAddress(&pkh, g_kh);
    cudaGetSymbolAddress(&pvh, g_vh);
    cudaGetSymbolAddress(&pwah, g_wa_h);
    cudaGetSymbolAddress(&pwph, g_wp_h);
    cudaGetSymbolAddress(&pwfh, g_wf_h);
    cudaGetSymbolAddress(&pw2h, g_w2_h);

    float* x1 = (float*)px1;
    __half* h  = (__half*)ph;
    __half* y  = (__half*)py;
    __half* fc = (__half*)pfc;
    __half* q  = (__half*)pq;
    __half* kh = (__half*)pkh;
    __half* vh = (__half*)pvh;
    __half* wah = (__half*)pwah;
    __half* wph = (__half*)pwph;
    __half* wfh = (__half*)pwfh;
    __half* w2h = (__half*)pw2h;

    static bool attr_done = false;
    if (!attr_done) {
        cudaFuncSetAttribute(mma_gemm<1>, cudaFuncAttributeMaxDynamicSharedMemorySize, GEMM_SMEM);
        cudaFuncSetAttribute(mma_gemm<2>, cudaFuncAttributeMaxDynamicSharedMemorySize, GEMM_SMEM);
        cudaFuncSetAttribute(mma_gemm<3>, cudaFuncAttributeMaxDynamicSharedMemorySize, GEMM_SMEM);
        cudaFuncSetAttribute(attn_mma,    cudaFuncAttributeMaxDynamicSharedMemorySize, ATT_SMEM);
        attr_done = true;
    }

    // 0) weight pre-conversion (fp32 -> fp16, one launch)
    conv_all<<<(N4_TOT + 255)/256, 256>>>(w_attn, w_proj, w_fc, w_fc2);

    // 1) h = LN1(x)
    ln_kernel<<<Mrows, 256>>>(x, ln1_w, ln1_b, h);
    // 2) QKV GEMM -> q (fp16, x0.125) / k / v, [B,H,L,D]
    mma_gemm<3><<<dim3(3*Cx/128, Mrows/128), 256, GEMM_SMEM>>>(
        h, wah, b_attn, nullptr, nullptr, nullptr,
        q, kh, vh, Mrows, 3*Cx, Cx);
    // 3) y = causal flash attention (fp16)
    attn_mma<<<dim3(Lx/64, Bsz*Hx), 128, ATT_SMEM>>>(q, kh, vh, y);
    // 4) x1 = x + y @ w_proj + b_proj
    mma_gemm<2><<<dim3(Cx/128, Mrows/128), 256, GEMM_SMEM>>>(
        y, wph, b_proj, x, x1, nullptr,
        nullptr, nullptr, nullptr, Mrows, Cx, Cx);
    // 5) h = LN2(x1)
    ln_kernel<<<Mrows, 256>>>(x1, ln2_w, ln2_b, h);
    // 6) fc = gelu(h @ w_fc + b_fc) -> fp16
    mma_gemm<1><<<dim3(4*Cx/128, Mrows/128), 256, GEMM_SMEM>>>(
        h, wfh, b_fc, nullptr, nullptr, fc,
        nullptr, nullptr, nullptr, Mrows, 4*Cx, Cx);
    // 7) out = x1 + fc @ w_fc2 + b_fc2
    mma_gemm<2><<<dim3(Cx/128, Mrows/128), 256, GEMM_SMEM>>>(
        fc, w2h, b_fc2, x1, out, nullptr,
        nullptr, nullptr, nullptr, Mrows, Cx, 4*Cx);
}

// round 16
// speedup vs baseline: 1.7395x; 1.0603x over previous
#include <cuda_runtime.h>
#include <cuda_fp16.h>
#include <math.h>
#include <stdint.h>

// Problem constants
#define Bsz 2
#define Lx  2048
#define Cx  1024
#define Hx  16
#define Dx  64
#define Mrows (Bsz*Lx)      // 4096

// ---------------- scratch (__device__ globals: alloc-free) ----------------
__device__ float g_x1 [Mrows * Cx];

__device__ __half g_h  [Mrows * Cx];
__device__ __half g_y  [Mrows * Cx];
__device__ __half g_fc [Mrows * 4 * Cx];

// attention operands, [B,H,L,D] (single fp16)
__device__ __half g_q  [Mrows * Cx];
__device__ __half g_kh [Mrows * Cx];
__device__ __half g_vh [Mrows * Cx];

// weights: fp16
__device__ __half g_wa_h [Cx * 3 * Cx];
__device__ __half g_wp_h [Cx * Cx];
__device__ __half g_wf_h [Cx * 4 * Cx];
__device__ __half g_w2_h [4 * Cx * Cx];

// ================= helpers ==========================
__device__ __forceinline__ uint32_t smem_u32(const void* p) {
    uint32_t a;
    asm("{ .reg .u64 t; cvta.to.shared.u64 t, %1; cvt.u32.u64 %0, t; }"
        : "=r"(a) : "l"(p));
    return a;
}
__device__ __forceinline__ uint32_t pack_h(float a, float b) {
    __half2 h = __floats2half2_rn(a, b);
    return *(uint32_t*)&h;
}

__device__ __forceinline__ void cp16(uint32_t dst, const void* src) {
    asm volatile("cp.async.cg.shared.global [%0], [%1], 16;"
                 :: "r"(dst), "l"(src));
}
#define CP_COMMIT() asm volatile("cp.async.commit_group;" ::: "memory")
#define CP_WAIT0()  asm volatile("cp.async.wait_group 0;" ::: "memory")
#define CP_WAIT2()  asm volatile("cp.async.wait_group 2;" ::: "memory")

__device__ __forceinline__ void ldsm4(uint32_t (&r)[4], uint32_t addr) {
    asm volatile("ldmatrix.sync.aligned.m8n8.x4.shared.b16 {%0,%1,%2,%3}, [%4];"
                 : "=r"(r[0]), "=r"(r[1]), "=r"(r[2]), "=r"(r[3]) : "r"(addr));
}
__device__ __forceinline__ void ldsm4t(uint32_t (&r)[4], uint32_t addr) {
    asm volatile("ldmatrix.sync.aligned.m8n8.x4.trans.shared.b16 {%0,%1,%2,%3}, [%4];"
                 : "=r"(r[0]), "=r"(r[1]), "=r"(r[2]), "=r"(r[3]) : "r"(addr));
}
__device__ __forceinline__ void mma_f16(float (&c)[4], const uint32_t (&a)[4],
                                        uint32_t b0, uint32_t b1) {
    asm volatile(
        "mma.sync.aligned.m16n8k16.row.col.f32.f16.f16.f32 "
        "{%0,%1,%2,%3},{%4,%5,%6,%7},{%8,%9},{%0,%1,%2,%3};"
        : "+f"(c[0]), "+f"(c[1]), "+f"(c[2]), "+f"(c[3])
        : "r"(a[0]), "r"(a[1]), "r"(a[2]), "r"(a[3]), "r"(b0), "r"(b1));
}

__device__ __forceinline__ float gelu_f(float x) {
    float x3 = x * x * x;
    float t  = tanhf(0.7978845608028654f * (x + 0.044715f * x3));
    return 0.5f * x * (1.0f + t);
}

// MUFU exp2 (single-instruction)
__device__ __forceinline__ float fexp2(float t) {
    float r;
    asm("ex2.approx.ftz.f32 %0, %1;" : "=f"(r) : "f"(t));
    return r;
}
#define LOG2E 1.4426950408889634f

// -------- single-launch weight conversion (fp32 -> fp16) ------------------
#define N4_WA 786432
#define N4_WP 262144
#define N4_WF 1048576
#define N4_W2 1048576
#define N4_TOT (N4_WA + N4_WP + N4_WF + N4_W2)

__global__ __launch_bounds__(256) void conv_all(
    const float* __restrict__ wa, const float* __restrict__ wp,
    const float* __restrict__ wf, const float* __restrict__ w2)
{
    int i = blockIdx.x * 256 + threadIdx.x;
    if (i >= N4_TOT) return;
    const float* src;
    __half* hi;
    int j = i;
    if (j < N4_WA) {
        src = wa; hi = g_wa_h;
    } else if ((j -= N4_WA) < N4_WP) {
        src = wp; hi = g_wp_h;
    } else if ((j -= N4_WP) < N4_WF) {
        src = wf; hi = g_wf_h;
    } else {
        j -= N4_WF;
        src = w2; hi = g_w2_h;
    }
    float4 v = ((const float4*)src)[j];
    ((uint2*)hi)[j] = make_uint2(pack_h(v.x, v.y), pack_h(v.z, v.w));
}

// =========================================================================
// Plain fp16 GEMM (fp32 accum). 4-warp CTA, tile 128x128, warp tile 64x64
// (A-fragment redundancy 4->2: crossbar relief). BK=32, 4-stage ring,
// one sync per chunk, 2 CTAs/SM.
// EPI: 1 = bias+gelu -> fp16; 2 = bias+residual -> fp32
//      3 = bias, split Q(x0.125)/K/V fp16 in [B,H,L,D]
// =========================================================================
#define A_STRIDE 80
#define B_STRIDE 272
#define SZ_A (128 * A_STRIDE)          // 10240
#define SZ_B (32 * B_STRIDE)           // 8704
#define OFF_B  SZ_A
#define STAGE_BYTES (SZ_A + SZ_B)      // 18944
#define GEMM_SMEM (4 * STAGE_BYTES)    // 75776 -> 2 CTAs/SM

template<int EPI>
__global__ __launch_bounds__(128, 2) void mma_gemm(
    const __half* __restrict__ A,
    const __half* __restrict__ Wh,
    const float* __restrict__ bias, const float* __restrict__ res,
    float* __restrict__ outf, __half* __restrict__ outh,
    __half* __restrict__ q_, __half* __restrict__ kh_, __half* __restrict__ vh_,
    int M, int N, int K)
{
    extern __shared__ char smem_raw[];
    const uint32_t sm = smem_u32(smem_raw);

    const int tid  = threadIdx.x;
    const int wid  = tid >> 5;
    const int lane = tid & 31;
    const int bm   = blockIdx.y * 128;
    const int bn   = blockIdx.x * 128;
    const int wm   = wid >> 1;          // 0..1
    const int wn   = wid & 1;           // 0..1
    const int nch  = K >> 5;

    float acc[4][8][4];                  // 64 (M) x 64 (N) per warp
    #pragma unroll
    for (int i = 0; i < 4; i++)
        #pragma unroll
        for (int j = 0; j < 8; j++)
            #pragma unroll
            for (int q = 0; q < 4; q++) acc[i][j][q] = 0.f;

    auto load_stage = [&](int c) {
        if (c < nch) {
            const int s  = c & 3;
            const int k0 = c << 5;
            const uint32_t sb = sm + s * STAGE_BYTES;
            // A: 128 rows x 32 halves = 512 segs, 4/thread
            #pragma unroll
            for (int u = 0; u < 4; u++) {
                int f   = u * 128 + tid;
                int row = f >> 2, seg = f & 3;
                cp16(sb + row * A_STRIDE + seg * 16,
                     A + (size_t)(bm + row) * K + k0 + seg * 8);
            }
            // B: 32 k-rows x 128 n = 512 segs, 4/thread
            #pragma unroll
            for (int u = 0; u < 4; u++) {
                int i  = u * 128 + tid;
                int kr = i >> 4, seg = i & 15;
                cp16(sb + OFF_B + kr * B_STRIDE + seg * 16,
                     Wh + (size_t)(k0 + kr) * N + bn + seg * 8);
            }
        }
        CP_COMMIT();
    };

    load_stage(0);
    load_stage(1);
    load_stage(2);

    const int lr = lane & 15;
    const int lc = lane >> 4;

    for (int c = 0; c < nch; c++) {
        CP_WAIT2();              // stage c landed (c+1, c+2 may be pending)
        __syncthreads();         // all warps done with compute(c-1)
        load_stage(c + 3);       // writes (c+3)&3 == (c-1)&3: safe after sync

        const uint32_t sb = sm + (c & 3) * STAGE_BYTES;

        #pragma unroll
        for (int ks = 0; ks < 2; ks++) {
            uint32_t ah[4][4];
            #pragma unroll
            for (int mf = 0; mf < 4; mf++) {
                uint32_t ao = sb + (wm * 64 + mf * 16 + lr) * A_STRIDE
                            + lc * 16 + ks * 32;     // ks*16 halves
                ldsm4(ah[mf], ao);
            }
            #pragma unroll
            for (int bt = 0; bt < 4; bt++) {
                uint32_t b4[4];
                uint32_t bo = sb + OFF_B + (ks * 16 + lr) * B_STRIDE
                            + (wn * 64 + bt * 16 + lc * 8) * 2;
                ldsm4t(b4, bo);
                #pragma unroll
                for (int mf = 0; mf < 4; mf++) {
                    mma_f16(acc[mf][bt*2],   ah[mf], b4[0], b4[1]);
                    mma_f16(acc[mf][bt*2+1], ah[mf], b4[2], b4[3]);
                }
            }
        }
    }

    // ---- epilogue: warp covers rows wm*64..+64, cols wn*64..+64 ----
    #pragma unroll
    for (int mf = 0; mf < 4; mf++) {
        #pragma unroll
        for (int nf = 0; nf < 8; nf++) {
            int col = bn + wn * 64 + nf * 8 + (lane & 3) * 2;
            float2 bv = *(const float2*)(bias + col);
            #pragma unroll
            for (int half = 0; half < 2; half++) {
                int row = bm + wm * 64 + mf * 16 + (lane >> 2) + half * 8;
                float v0 = acc[mf][nf][half * 2 + 0] + bv.x;
                float v1 = acc[mf][nf][half * 2 + 1] + bv.y;
                if (EPI == 1) {
                    v0 = gelu_f(v0); v1 = gelu_f(v1);
                    *(uint32_t*)(outh + (size_t)row * N + col) = pack_h(v0, v1);
                } else if (EPI == 3) {
                    int sector = col >> 10;
                    int wcol = col & 1023;
                    int hh = wcol >> 6;
                    int dd = wcol & 63;
                    int brow = row >> 11;
                    int lrow = row & 2047;
                    size_t dst = ((size_t)(brow * Hx + hh) * Lx + lrow) * Dx + dd;
                    if (sector == 0) {
                        *(uint32_t*)(q_ + dst) = pack_h(v0 * 0.125f, v1 * 0.125f);
                    } else if (sector == 1) {
                        *(uint32_t*)(kh_ + dst) = pack_h(v0, v1);
                    } else {
                        *(uint32_t*)(vh_ + dst) = pack_h(v0, v1);
                    }
                } else {
                    float2 rv = *(const float2*)(res + (size_t)row * N + col);
                    v0 += rv.x; v1 += rv.y;
                    *(float2*)(outf + (size_t)row * N + col) = make_float2(v0, v1);
                }
            }
        }
    }
}

// ---------------- LayerNorm -> fp16 output --------------------------------
__global__ __launch_bounds__(256) void ln_kernel(const float* __restrict__ x,
                                                 const float* __restrict__ w,
                                                 const float* __restrict__ b,
                                                 __half* __restrict__ oh)
{
    int row = blockIdx.x;
    int t   = threadIdx.x;
    const float4* xr = (const float4*)(x + (size_t)row * Cx);
    float4 v = xr[t];
    float s  = v.x + v.y + v.z + v.w;
    float sq = v.x*v.x + v.y*v.y + v.z*v.z + v.w*v.w;
    #pragma unroll
    for (int o = 16; o > 0; o >>= 1) {
        s  += __shfl_xor_sync(0xffffffffu, s,  o);
        sq += __shfl_xor_sync(0xffffffffu, sq, o);
    }
    __shared__ float ss[8], ssq[8];
    int wid = t >> 5, lane = t & 31;
    if (lane == 0) { ss[wid] = s; ssq[wid] = sq; }
    __syncthreads();
    float tot = 0.f, totq = 0.f;
    #pragma unroll
    for (int i = 0; i < 8; i++) { tot += ss[i]; totq += ssq[i]; }
    float mean = tot * (1.0f / Cx);
    float var  = totq * (1.0f / Cx) - mean * mean;
    float rstd = rsqrtf(var + 1e-5f);
    const float4 wv = ((const float4*)w)[t];
    const float4 bv = ((const float4*)b)[t];
    float o0 = (v.x - mean) * rstd * wv.x + bv.x;
    float o1 = (v.y - mean) * rstd * wv.y + bv.y;
    float o2 = (v.z - mean) * rstd * wv.z + bv.z;
    float o3 = (v.w - mean) * rstd * wv.w + bv.w;
    size_t idx = (size_t)row * Cx + t * 4;
    *(uint2*)(oh + idx) = make_uint2(pack_h(o0, o1), pack_h(o2, o3));
}

// =========================================================================
// Tensor-core causal flash attention, pure fp16, MUFU exp2.
// 128 threads (4 warps), 64 q-rows/CTA, 2-stage KV ring, 46 KB smem.
// =========================================================================
#define QSTR 144
#define ATT_QS   9216
#define ATT_KVS  9216
#define ATT_STG  (2*ATT_KVS)           // 18432 (K + V)
#define ATT_SMEM (ATT_QS + 2*ATT_STG)  // 46080

__global__ __launch_bounds__(128, 3) void attn_mma(
    const __half* __restrict__ q_,
    const __half* __restrict__ kh_,
    const __half* __restrict__ vh_,
    __half* __restrict__ y_)
{
    extern __shared__ char sm_raw[];
    const uint32_t S = smem_u32(sm_raw);
    const int tid = threadIdx.x, wid = tid >> 5, lane = tid & 31;
    const int qt  = gridDim.x - 1 - blockIdx.x;   // heavy CTAs first
    const int qb  = qt * 64;
    const int bh  = blockIdx.y;
    const size_t hb = (size_t)bh * Lx * Dx;

    const __half *Q  = q_  + hb;
    const __half *Kh = kh_ + hb;
    const __half *Vh = vh_ + hb;

    const int nk = qt + 1;

    auto load_kv = [&](int kt) {
        if (kt < nk) {
            const uint32_t db = S + ATT_QS + (kt & 1) * ATT_STG;
            #pragma unroll
            for (int u = 0; u < 8; u++) {
                int j = u * 128 + tid;
                int arr = j >> 9;              // 0 = K, 1 = V
                int rem = j & 511;
                int row = rem >> 3, seg = rem & 7;
                const __half* src = (arr == 0) ? Kh : Vh;
                cp16(db + arr * ATT_KVS + row * QSTR + seg * 16,
                     src + (size_t)(kt * 64 + row) * Dx + seg * 8);
            }
        }
        CP_COMMIT();
    };

    // prologue: {Q, kv0} in one group
    #pragma unroll
    for (int u = 0; u < 4; u++) {
        int j = u * 128 + tid;
        int row = j >> 3, seg = j & 7;
        cp16(S + row * QSTR + seg * 16,
             Q + (size_t)(qb + row) * Dx + seg * 8);
    }
    {
        const uint32_t db = S + ATT_QS;
        #pragma unroll
        for (int u = 0; u < 8; u++) {
            int j = u * 128 + tid;
            int arr = j >> 9;
            int rem = j & 511;
            int row = rem >> 3, seg = rem & 7;
            const __half* src = (arr == 0) ? Kh : Vh;
            cp16(db + arr * ATT_KVS + row * QSTR + seg * 16,
                 src + (size_t)row * Dx + seg * 8);
        }
        CP_COMMIT();
    }

    uint32_t qf[4][4];
    float oc[8][4];
    #pragma unroll
    for (int d = 0; d < 8; d++)
        #pragma unroll
        for (int i = 0; i < 4; i++) oc[d][i] = 0.f;
    float m0 = -1e30f, m1 = -1e30f, l0 = 0.f, l1 = 0.f;

    const int r0g = qb + wid * 16 + (lane >> 2);

    for (int kt = 0; kt < nk; kt++) {
        CP_WAIT0();              // kv(kt) arrived
        __syncthreads();         // all warps done with tile kt-1
        if (kt == 0) {
            #pragma unroll
            for (int ks = 0; ks < 4; ks++) {
                uint32_t ao = S + (wid * 16 + (lane & 15)) * QSTR
                            + (lane >> 4) * 16 + ks * 32;
                ldsm4(qf[ks], ao);
            }
        }
        load_kv(kt + 1);         // writes stage (kt+1)&1, reused from kt-1: safe

        const int k0 = kt * 64;
        const uint32_t kb = S + ATT_QS + (kt & 1) * ATT_STG;

        // ---- S = Q @ K^T (fp16) ----
        float sc[8][4];
        #pragma unroll
        for (int nt = 0; nt < 8; nt++)
            #pragma unroll
            for (int i = 0; i < 4; i++) sc[nt][i] = 0.f;

        #pragma unroll
        for (int ks = 0; ks < 4; ks++) {
            uint32_t k4[4][4];
            #pragma unroll
            for (int ntp = 0; ntp < 4; ntp++) {
                uint32_t ad = kb
                    + (uint32_t)((ntp * 16 + (lane & 7) + ((lane >> 4) << 3)) * QSTR)
                    + ((lane >> 3) & 1) * 16 + ks * 32;
                ldsm4(k4[ntp], ad);
            }
            #pragma unroll
            for (int ntp = 0; ntp < 4; ntp++)
                #pragma unroll
                for (int hf = 0; hf < 2; hf++) {
                    int nt = ntp * 2 + hf, p = hf * 2;
                    mma_f16(sc[nt], qf[ks], k4[ntp][p], k4[ntp][p + 1]);
                }
        }

        // ---- causal mask (diagonal tile only) ----
        if (kt == qt) {
            #pragma unroll
            for (int nt = 0; nt < 8; nt++) {
                int key = k0 + nt * 8 + (lane & 3) * 2;
                if (key     > r0g)     sc[nt][0] = -1e30f;
                if (key + 1 > r0g)     sc[nt][1] = -1e30f;
                if (key     > r0g + 8) sc[nt][2] = -1e30f;
                if (key + 1 > r0g + 8) sc[nt][3] = -1e30f;
            }
        }

        // ---- online softmax (MUFU exp2) ----
        float rm0 = -1e30f, rm1 = -1e30f;
        #pragma unroll
        for (int nt = 0; nt < 8; nt++) {
            rm0 = fmaxf(rm0, fmaxf(sc[nt][0], sc[nt][1]));
            rm1 = fmaxf(rm1, fmaxf(sc[nt][2], sc[nt][3]));
        }
        rm0 = fmaxf(rm0, __shfl_xor_sync(0xffffffffu, rm0, 1));
        rm0 = fmaxf(rm0, __shfl_xor_sync(0xffffffffu, rm0, 2));
        rm1 = fmaxf(rm1, __shfl_xor_sync(0xffffffffu, rm1, 1));
        rm1 = fmaxf(rm1, __shfl_xor_sync(0xffffffffu, rm1, 2));
        float mn0 = fmaxf(m0, rm0 * LOG2E);
        float mn1 = fmaxf(m1, rm1 * LOG2E);
        float s0 = fexp2(m0 - mn0);
        float s1 = fexp2(m1 - mn1);
        m0 = mn0; m1 = mn1;
        l0 *= s0; l1 *= s1;
        #pragma unroll
        for (int d = 0; d < 8; d++) {
            oc[d][0] *= s0; oc[d][1] *= s0;
            oc[d][2] *= s1; oc[d][3] *= s1;
        }

        uint32_t pa[4][4];
        float la0 = 0.f, la1 = 0.f;
        #pragma unroll
        for (int nt = 0; nt < 8; nt++) {
            float p0 = fexp2(fmaf(sc[nt][0], LOG2E, -m0));
            float p1 = fexp2(fmaf(sc[nt][1], LOG2E, -m0));
            float p2 = fexp2(fmaf(sc[nt][2], LOG2E, -m1));
            float p3 = fexp2(fmaf(sc[nt][3], LOG2E, -m1));
            la0 += p0 + p1;
            la1 += p2 + p3;
            int ks2 = nt >> 1, idx = (nt & 1) * 2;
            pa[ks2][idx]     = pack_h(p0, p1);
            pa[ks2][idx + 1] = pack_h(p2, p3);
        }
        l0 += la0; l1 += la1;

        // ---- O += P @ V (fp16) ----
        #pragma unroll
        for (int ks2 = 0; ks2 < 4; ks2++) {
            uint32_t v4[4][4];
            #pragma unroll
            for (int dtp = 0; dtp < 4; dtp++) {
                uint32_t ad = kb + ATT_KVS
                    + (uint32_t)((ks2 * 16 + (lane & 15)) * QSTR)
                    + (dtp * 16 + (lane >> 4) * 8) * 2;
                ldsm4t(v4[dtp], ad);
            }
            #pragma unroll
            for (int dtp = 0; dtp < 4; dtp++)
                #pragma unroll
                for (int hf = 0; hf < 2; hf++) {
                    int dt = dtp * 2 + hf, p = hf * 2;
                    mma_f16(oc[dt], pa[ks2], v4[dtp][p], v4[dtp][p + 1]);
                }
        }
    }

    // ---- finalize ----
    l0 += __shfl_xor_sync(0xffffffffu, l0, 1);
    l0 += __shfl_xor_sync(0xffffffffu, l0, 2);
    l1 += __shfl_xor_sync(0xffffffffu, l1, 1);
    l1 += __shfl_xor_sync(0xffffffffu, l1, 2);
    float i0 = 1.f / l0, i1 = 1.f / l1;

    const int b  = bh >> 4;
    const int hh = bh & 15;
    const size_t row0 = (size_t)b * Lx + qb + wid * 16 + (lane >> 2);
    const int colb = hh * 64 + (lane & 3) * 2;
    #pragma unroll
    for (int dt = 0; dt < 8; dt++) {
        float a0 = oc[dt][0] * i0, a1 = oc[dt][1] * i0;
        float a2 = oc[dt][2] * i1, a3 = oc[dt][3] * i1;
        *(uint32_t*)(y_ + row0 * Cx + colb + dt * 8)       = pack_h(a0, a1);
        *(uint32_t*)(y_ + (row0 + 8) * Cx + colb + dt * 8) = pack_h(a2, a3);
    }
}

// ---------------- launcher ----------------
extern "C" void kernel_launch(void* const* d_in, const int* in_sizes, int n_in,
                              void* d_out, int out_size)
{
    const float* x      = (const float*)d_in[0];
    const float* ln1_w  = (const float*)d_in[1];
    const float* ln1_b  = (const float*)d_in[2];
    const float* w_attn = (const float*)d_in[3];
    const float* b_attn = (const float*)d_in[4];
    const float* w_proj = (const float*)d_in[5];
    const float* b_proj = (const float*)d_in[6];
    const float* ln2_w  = (const float*)d_in[7];
    const float* ln2_b  = (const float*)d_in[8];
    const float* w_fc   = (const float*)d_in[9];
    const float* b_fc   = (const float*)d_in[10];
    const float* w_fc2  = (const float*)d_in[11];
    const float* b_fc2  = (const float*)d_in[12];
    float* out = (float*)d_out;

    void *px1, *ph, *py, *pfc, *pq, *pkh, *pvh;
    void *pwah, *pwph, *pwfh, *pw2h;
    cudaGetSymbolAddress(&px1, g_x1);
    cudaGetSymbolAddress(&ph,  g_h);
    cudaGetSymbolAddress(&py,  g_y);
    cudaGetSymbolAddress(&pfc, g_fc);
    cudaGetSymbolAddress(&pq,  g_q);
    cudaGetSymbolAddress(&pkh, g_kh);
    cudaGetSymbolAddress(&pvh, g_vh);
    cudaGetSymbolAddress(&pwah, g_wa_h);
    cudaGetSymbolAddress(&pwph, g_wp_h);
    cudaGetSymbolAddress(&pwfh, g_wf_h);
    cudaGetSymbolAddress(&pw2h, g_w2_h);

    float* x1 = (float*)px1;
    __half* h  = (__half*)ph;
    __half* y  = (__half*)py;
    __half* fc = (__half*)pfc;
    __half* q  = (__half*)pq;
    __half* kh = (__half*)pkh;
    __half* vh = (__half*)pvh;
    __half* wah = (__half*)pwah;
    __half* wph = (__half*)pwph;
    __half* wfh = (__half*)pwfh;
    __half* w2h = (__half*)pw2h;

    static bool attr_done = false;
    if (!attr_done) {
        cudaFuncSetAttribute(mma_gemm<1>, cudaFuncAttributeMaxDynamicSharedMemorySize, GEMM_SMEM);
        cudaFuncSetAttribute(mma_gemm<2>, cudaFuncAttributeMaxDynamicSharedMemorySize, GEMM_SMEM);
        cudaFuncSetAttribute(mma_gemm<3>, cudaFuncAttributeMaxDynamicSharedMemorySize, GEMM_SMEM);
        cudaFuncSetAttribute(attn_mma,    cudaFuncAttributeMaxDynamicSharedMemorySize, ATT_SMEM);
        attr_done = true;
    }

    // 0) weight pre-conversion (fp32 -> fp16, one launch)
    conv_all<<<(N4_TOT + 255)/256, 256>>>(w_attn, w_proj, w_fc, w_fc2);

    // 1) h = LN1(x)
    ln_kernel<<<Mrows, 256>>>(x, ln1_w, ln1_b, h);
    // 2) QKV GEMM -> q (fp16, x0.125) / k / v, [B,H,L,D]
    mma_gemm<3><<<dim3(3*Cx/128, Mrows/128), 128, GEMM_SMEM>>>(
        h, wah, b_attn, nullptr, nullptr, nullptr,
        q, kh, vh, Mrows, 3*Cx, Cx);
    // 3) y = causal flash attention (fp16)
    attn_mma<<<dim3(Lx/64, Bsz*Hx), 128, ATT_SMEM>>>(q, kh, vh, y);
    // 4) x1 = x + y @ w_proj + b_proj
    mma_gemm<2><<<dim3(Cx/128, Mrows/128), 128, GEMM_SMEM>>>(
        y, wph, b_proj, x, x1, nullptr,
        nullptr, nullptr, nullptr, Mrows, Cx, Cx);
    // 5) h = LN2(x1)
    ln_kernel<<<Mrows, 256>>>(x1, ln2_w, ln2_b, h);
    // 6) fc = gelu(h @ w_fc + b_fc) -> fp16
    mma_gemm<1><<<dim3(4*Cx/128, Mrows/128), 128, GEMM_SMEM>>>(
        h, wfh, b_fc, nullptr, nullptr, fc,
        nullptr, nullptr, nullptr, Mrows, 4*Cx, Cx);
    // 7) out = x1 + fc @ w_fc2 + b_fc2
    mma_gemm<2><<<dim3(Cx/128, Mrows/128), 128, GEMM_SMEM>>>(
        fc, w2h, b_fc2, x1, out, nullptr,
        nullptr, nullptr, nullptr, Mrows, Cx, 4*Cx);
}

// round 17
// speedup vs baseline: 1.7469x; 1.0043x over previous
#include <cuda_runtime.h>
#include <cuda_fp16.h>
#include <math.h>
#include <stdint.h>

// Problem constants
#define Bsz 2
#define Lx  2048
#define Cx  1024
#define Hx  16
#define Dx  64
#define Mrows (Bsz*Lx)      // 4096

// ---------------- scratch (__device__ globals: alloc-free) ----------------
__device__ float g_x1 [Mrows * Cx];

__device__ __half g_h  [Mrows * Cx];
__device__ __half g_y  [Mrows * Cx];
__device__ __half g_fc [Mrows * 4 * Cx];

// attention operands, [B,H,L,D] (single fp16)
__device__ __half g_q  [Mrows * Cx];
__device__ __half g_kh [Mrows * Cx];
__device__ __half g_vh [Mrows * Cx];

// weights: fp16
__device__ __half g_wa_h [Cx * 3 * Cx];
__device__ __half g_wp_h [Cx * Cx];
__device__ __half g_wf_h [Cx * 4 * Cx];
__device__ __half g_w2_h [4 * Cx * Cx];

// ================= helpers ==========================
__device__ __forceinline__ uint32_t smem_u32(const void* p) {
    uint32_t a;
    asm("{ .reg .u64 t; cvta.to.shared.u64 t, %1; cvt.u32.u64 %0, t; }"
        : "=r"(a) : "l"(p));
    return a;
}
__device__ __forceinline__ uint32_t pack_h(float a, float b) {
    __half2 h = __floats2half2_rn(a, b);
    return *(uint32_t*)&h;
}

__device__ __forceinline__ void cp16(uint32_t dst, const void* src) {
    asm volatile("cp.async.cg.shared.global [%0], [%1], 16;"
                 :: "r"(dst), "l"(src));
}
#define CP_COMMIT() asm volatile("cp.async.commit_group;" ::: "memory")
#define CP_WAIT0()  asm volatile("cp.async.wait_group 0;" ::: "memory")
#define CP_WAIT2()  asm volatile("cp.async.wait_group 2;" ::: "memory")

__device__ __forceinline__ void ldsm4(uint32_t (&r)[4], uint32_t addr) {
    asm volatile("ldmatrix.sync.aligned.m8n8.x4.shared.b16 {%0,%1,%2,%3}, [%4];"
                 : "=r"(r[0]), "=r"(r[1]), "=r"(r[2]), "=r"(r[3]) : "r"(addr));
}
__device__ __forceinline__ void ldsm4t(uint32_t (&r)[4], uint32_t addr) {
    asm volatile("ldmatrix.sync.aligned.m8n8.x4.trans.shared.b16 {%0,%1,%2,%3}, [%4];"
                 : "=r"(r[0]), "=r"(r[1]), "=r"(r[2]), "=r"(r[3]) : "r"(addr));
}
__device__ __forceinline__ void mma_f16(float (&c)[4], const uint32_t (&a)[4],
                                        uint32_t b0, uint32_t b1) {
    asm volatile(
        "mma.sync.aligned.m16n8k16.row.col.f32.f16.f16.f32 "
        "{%0,%1,%2,%3},{%4,%5,%6,%7},{%8,%9},{%0,%1,%2,%3};"
        : "+f"(c[0]), "+f"(c[1]), "+f"(c[2]), "+f"(c[3])
        : "r"(a[0]), "r"(a[1]), "r"(a[2]), "r"(a[3]), "r"(b0), "r"(b1));
}

__device__ __forceinline__ float gelu_f(float x) {
    float x3 = x * x * x;
    float t  = tanhf(0.7978845608028654f * (x + 0.044715f * x3));
    return 0.5f * x * (1.0f + t);
}

// MUFU exp2 (single-instruction)
__device__ __forceinline__ float fexp2(float t) {
    float r;
    asm("ex2.approx.ftz.f32 %0, %1;" : "=f"(r) : "f"(t));
    return r;
}
#define LOG2E 1.4426950408889634f

// -------- single-launch weight conversion (fp32 -> fp16) ------------------
#define N4_WA 786432
#define N4_WP 262144
#define N4_WF 1048576
#define N4_W2 1048576
#define N4_TOT (N4_WA + N4_WP + N4_WF + N4_W2)

__global__ __launch_bounds__(256) void conv_all(
    const float* __restrict__ wa, const float* __restrict__ wp,
    const float* __restrict__ wf, const float* __restrict__ w2)
{
    int i = blockIdx.x * 256 + threadIdx.x;
    if (i >= N4_TOT) return;
    const float* src;
    __half* hi;
    int j = i;
    if (j < N4_WA) {
        src = wa; hi = g_wa_h;
    } else if ((j -= N4_WA) < N4_WP) {
        src = wp; hi = g_wp_h;
    } else if ((j -= N4_WP) < N4_WF) {
        src = wf; hi = g_wf_h;
    } else {
        j -= N4_WF;
        src = w2; hi = g_w2_h;
    }
    float4 v = ((const float4*)src)[j];
    ((uint2*)hi)[j] = make_uint2(pack_h(v.x, v.y), pack_h(v.z, v.w));
}

// =========================================================================
// Plain fp16 GEMM (fp32 accum). 4-warp CTA, tile 128x128, warp tile 64x64,
// BK=32, 4-stage ring, one sync per chunk, 2 CTAs/SM.
// Full fragment prefetch per chunk: 16 ldsm first, then 64 MMAs contiguous.
// EPI: 1 = bias+gelu -> fp16; 2 = bias+residual -> fp32
//      3 = bias, split Q(x0.125)/K/V fp16 in [B,H,L,D]
// =========================================================================
#define A_STRIDE 80
#define B_STRIDE 272
#define SZ_A (128 * A_STRIDE)          // 10240
#define SZ_B (32 * B_STRIDE)           // 8704
#define OFF_B  SZ_A
#define STAGE_BYTES (SZ_A + SZ_B)      // 18944
#define GEMM_SMEM (4 * STAGE_BYTES)    // 75776 -> 2 CTAs/SM

template<int EPI>
__global__ __launch_bounds__(128, 2) void mma_gemm(
    const __half* __restrict__ A,
    const __half* __restrict__ Wh,
    const float* __restrict__ bias, const float* __restrict__ res,
    float* __restrict__ outf, __half* __restrict__ outh,
    __half* __restrict__ q_, __half* __restrict__ kh_, __half* __restrict__ vh_,
    int M, int N, int K)
{
    extern __shared__ char smem_raw[];
    const uint32_t sm = smem_u32(smem_raw);

    const int tid  = threadIdx.x;
    const int wid  = tid >> 5;
    const int lane = tid & 31;
    const int bm   = blockIdx.y * 128;
    const int bn   = blockIdx.x * 128;
    const int wm   = wid >> 1;          // 0..1
    const int wn   = wid & 1;           // 0..1
    const int nch  = K >> 5;

    float acc[4][8][4];                  // 64 (M) x 64 (N) per warp
    #pragma unroll
    for (int i = 0; i < 4; i++)
        #pragma unroll
        for (int j = 0; j < 8; j++)
            #pragma unroll
            for (int q = 0; q < 4; q++) acc[i][j][q] = 0.f;

    auto load_stage = [&](int c) {
        if (c < nch) {
            const int s  = c & 3;
            const int k0 = c << 5;
            const uint32_t sb = sm + s * STAGE_BYTES;
            #pragma unroll
            for (int u = 0; u < 4; u++) {
                int f   = u * 128 + tid;
                int row = f >> 2, seg = f & 3;
                cp16(sb + row * A_STRIDE + seg * 16,
                     A + (size_t)(bm + row) * K + k0 + seg * 8);
            }
            #pragma unroll
            for (int u = 0; u < 4; u++) {
                int i  = u * 128 + tid;
                int kr = i >> 4, seg = i & 15;
                cp16(sb + OFF_B + kr * B_STRIDE + seg * 16,
                     Wh + (size_t)(k0 + kr) * N + bn + seg * 8);
            }
        }
        CP_COMMIT();
    };

    load_stage(0);
    load_stage(1);
    load_stage(2);

    const int lr = lane & 15;
    const int lc = lane >> 4;

    for (int c = 0; c < nch; c++) {
        CP_WAIT2();              // stage c landed
        __syncthreads();         // all warps done with compute(c-1)
        load_stage(c + 3);       // writes (c+3)&3 == (c-1)&3: safe after sync

        const uint32_t sb = sm + (c & 3) * STAGE_BYTES;

        // ---- prefetch ALL fragments for this chunk (16 ldsm) ----
        uint32_t ah[2][4][4], bh[2][4][4];
        #pragma unroll
        for (int ks = 0; ks < 2; ks++) {
            #pragma unroll
            for (int mf = 0; mf < 4; mf++) {
                uint32_t ao = sb + (wm * 64 + mf * 16 + lr) * A_STRIDE
                            + lc * 16 + ks * 32;
                ldsm4(ah[ks][mf], ao);
            }
            #pragma unroll
            for (int bt = 0; bt < 4; bt++) {
                uint32_t bo = sb + OFF_B + (ks * 16 + lr) * B_STRIDE
                            + (wn * 64 + bt * 16 + lc * 8) * 2;
                ldsm4t(bh[ks][bt], bo);
            }
        }

        // ---- 64 MMAs back-to-back ----
        #pragma unroll
        for (int ks = 0; ks < 2; ks++)
            #pragma unroll
            for (int bt = 0; bt < 4; bt++)
                #pragma unroll
                for (int mf = 0; mf < 4; mf++) {
                    mma_f16(acc[mf][bt*2],   ah[ks][mf], bh[ks][bt][0], bh[ks][bt][1]);
                    mma_f16(acc[mf][bt*2+1], ah[ks][mf], bh[ks][bt][2], bh[ks][bt][3]);
                }
    }

    // ---- epilogue: warp covers rows wm*64..+64, cols wn*64..+64 ----
    #pragma unroll
    for (int mf = 0; mf < 4; mf++) {
        #pragma unroll
        for (int nf = 0; nf < 8; nf++) {
            int col = bn + wn * 64 + nf * 8 + (lane & 3) * 2;
            float2 bv = *(const float2*)(bias + col);
            #pragma unroll
            for (int half = 0; half < 2; half++) {
                int row = bm + wm * 64 + mf * 16 + (lane >> 2) + half * 8;
                float v0 = acc[mf][nf][half * 2 + 0] + bv.x;
                float v1 = acc[mf][nf][half * 2 + 1] + bv.y;
                if (EPI == 1) {
                    v0 = gelu_f(v0); v1 = gelu_f(v1);
                    *(uint32_t*)(outh + (size_t)row * N + col) = pack_h(v0, v1);
                } else if (EPI == 3) {
                    int sector = col >> 10;
                    int wcol = col & 1023;
                    int hh = wcol >> 6;
                    int dd = wcol & 63;
                    int brow = row >> 11;
                    int lrow = row & 2047;
                    size_t dst = ((size_t)(brow * Hx + hh) * Lx + lrow) * Dx + dd;
                    if (sector == 0) {
                        *(uint32_t*)(q_ + dst) = pack_h(v0 * 0.125f, v1 * 0.125f);
                    } else if (sector == 1) {
                        *(uint32_t*)(kh_ + dst) = pack_h(v0, v1);
                    } else {
                        *(uint32_t*)(vh_ + dst) = pack_h(v0, v1);
                    }
                } else {
                    float2 rv = *(const float2*)(res + (size_t)row * N + col);
                    v0 += rv.x; v1 += rv.y;
                    *(float2*)(outf + (size_t)row * N + col) = make_float2(v0, v1);
                }
            }
        }
    }
}

// ---------------- LayerNorm -> fp16 output --------------------------------
__global__ __launch_bounds__(256) void ln_kernel(const float* __restrict__ x,
                                                 const float* __restrict__ w,
                                                 const float* __restrict__ b,
                                                 __half* __restrict__ oh)
{
    int row = blockIdx.x;
    int t   = threadIdx.x;
    const float4* xr = (const float4*)(x + (size_t)row * Cx);
    float4 v = xr[t];
    float s  = v.x + v.y + v.z + v.w;
    float sq = v.x*v.x + v.y*v.y + v.z*v.z + v.w*v.w;
    #pragma unroll
    for (int o = 16; o > 0; o >>= 1) {
        s  += __shfl_xor_sync(0xffffffffu, s,  o);
        sq += __shfl_xor_sync(0xffffffffu, sq, o);
    }
    __shared__ float ss[8], ssq[8];
    int wid = t >> 5, lane = t & 31;
    if (lane == 0) { ss[wid] = s; ssq[wid] = sq; }
    __syncthreads();
    float tot = 0.f, totq = 0.f;
    #pragma unroll
    for (int i = 0; i < 8; i++) { tot += ss[i]; totq += ssq[i]; }
    float mean = tot * (1.0f / Cx);
    float var  = totq * (1.0f / Cx) - mean * mean;
    float rstd = rsqrtf(var + 1e-5f);
    const float4 wv = ((const float4*)w)[t];
    const float4 bv = ((const float4*)b)[t];
    float o0 = (v.x - mean) * rstd * wv.x + bv.x;
    float o1 = (v.y - mean) * rstd * wv.y + bv.y;
    float o2 = (v.z - mean) * rstd * wv.z + bv.z;
    float o3 = (v.w - mean) * rstd * wv.w + bv.w;
    size_t idx = (size_t)row * Cx + t * 4;
    *(uint2*)(oh + idx) = make_uint2(pack_h(o0, o1), pack_h(o2, o3));
}

// =========================================================================
// Tensor-core causal flash attention, pure fp16, MUFU exp2 (R16, 73.9 us).
// =========================================================================
#define QSTR 144
#define ATT_QS   9216
#define ATT_KVS  9216
#define ATT_STG  (2*ATT_KVS)           // 18432 (K + V)
#define ATT_SMEM (ATT_QS + 2*ATT_STG)  // 46080

__global__ __launch_bounds__(128, 3) void attn_mma(
    const __half* __restrict__ q_,
    const __half* __restrict__ kh_,
    const __half* __restrict__ vh_,
    __half* __restrict__ y_)
{
    extern __shared__ char sm_raw[];
    const uint32_t S = smem_u32(sm_raw);
    const int tid = threadIdx.x, wid = tid >> 5, lane = tid & 31;
    const int qt  = gridDim.x - 1 - blockIdx.x;   // heavy CTAs first
    const int qb  = qt * 64;
    const int bh  = blockIdx.y;
    const size_t hb = (size_t)bh * Lx * Dx;

    const __half *Q  = q_  + hb;
    const __half *Kh = kh_ + hb;
    const __half *Vh = vh_ + hb;

    const int nk = qt + 1;

    auto load_kv = [&](int kt) {
        if (kt < nk) {
            const uint32_t db = S + ATT_QS + (kt & 1) * ATT_STG;
            #pragma unroll
            for (int u = 0; u < 8; u++) {
                int j = u * 128 + tid;
                int arr = j >> 9;              // 0 = K, 1 = V
                int rem = j & 511;
                int row = rem >> 3, seg = rem & 7;
                const __half* src = (arr == 0) ? Kh : Vh;
                cp16(db + arr * ATT_KVS + row * QSTR + seg * 16,
                     src + (size_t)(kt * 64 + row) * Dx + seg * 8);
            }
        }
        CP_COMMIT();
    };

    // prologue: {Q, kv0} in one group
    #pragma unroll
    for (int u = 0; u < 4; u++) {
        int j = u * 128 + tid;
        int row = j >> 3, seg = j & 7;
        cp16(S + row * QSTR + seg * 16,
             Q + (size_t)(qb + row) * Dx + seg * 8);
    }
    {
        const uint32_t db = S + ATT_QS;
        #pragma unroll
        for (int u = 0; u < 8; u++) {
            int j = u * 128 + tid;
            int arr = j >> 9;
            int rem = j & 511;
            int row = rem >> 3, seg = rem & 7;
            const __half* src = (arr == 0) ? Kh : Vh;
            cp16(db + arr * ATT_KVS + row * QSTR + seg * 16,
                 src + (size_t)row * Dx + seg * 8);
        }
        CP_COMMIT();
    }

    uint32_t qf[4][4];
    float oc[8][4];
    #pragma unroll
    for (int d = 0; d < 8; d++)
        #pragma unroll
        for (int i = 0; i < 4; i++) oc[d][i] = 0.f;
    float m0 = -1e30f, m1 = -1e30f, l0 = 0.f, l1 = 0.f;

    const int r0g = qb + wid * 16 + (lane >> 2);

    for (int kt = 0; kt < nk; kt++) {
        CP_WAIT0();              // kv(kt) arrived
        __syncthreads();         // all warps done with tile kt-1
        if (kt == 0) {
            #pragma unroll
            for (int ks = 0; ks < 4; ks++) {
                uint32_t ao = S + (wid * 16 + (lane & 15)) * QSTR
                            + (lane >> 4) * 16 + ks * 32;
                ldsm4(qf[ks], ao);
            }
        }
        load_kv(kt + 1);         // writes stage (kt+1)&1, reused from kt-1: safe

        const int k0 = kt * 64;
        const uint32_t kb = S + ATT_QS + (kt & 1) * ATT_STG;

        // ---- S = Q @ K^T (fp16) ----
        float sc[8][4];
        #pragma unroll
        for (int nt = 0; nt < 8; nt++)
            #pragma unroll
            for (int i = 0; i < 4; i++) sc[nt][i] = 0.f;

        #pragma unroll
        for (int ks = 0; ks < 4; ks++) {
            uint32_t k4[4][4];
            #pragma unroll
            for (int ntp = 0; ntp < 4; ntp++) {
                uint32_t ad = kb
                    + (uint32_t)((ntp * 16 + (lane & 7) + ((lane >> 4) << 3)) * QSTR)
                    + ((lane >> 3) & 1) * 16 + ks * 32;
                ldsm4(k4[ntp], ad);
            }
            #pragma unroll
            for (int ntp = 0; ntp < 4; ntp++)
                #pragma unroll
                for (int hf = 0; hf < 2; hf++) {
                    int nt = ntp * 2 + hf, p = hf * 2;
                    mma_f16(sc[nt], qf[ks], k4[ntp][p], k4[ntp][p + 1]);
                }
        }

        // ---- causal mask (diagonal tile only) ----
        if (kt == qt) {
            #pragma unroll
            for (int nt = 0; nt < 8; nt++) {
                int key = k0 + nt * 8 + (lane & 3) * 2;
                if (key     > r0g)     sc[nt][0] = -1e30f;
                if (key + 1 > r0g)     sc[nt][1] = -1e30f;
                if (key     > r0g + 8) sc[nt][2] = -1e30f;
                if (key + 1 > r0g + 8) sc[nt][3] = -1e30f;
            }
        }

        // ---- online softmax (MUFU exp2) ----
        float rm0 = -1e30f, rm1 = -1e30f;
        #pragma unroll
        for (int nt = 0; nt < 8; nt++) {
            rm0 = fmaxf(rm0, fmaxf(sc[nt][0], sc[nt][1]));
            rm1 = fmaxf(rm1, fmaxf(sc[nt][2], sc[nt][3]));
        }
        rm0 = fmaxf(rm0, __shfl_xor_sync(0xffffffffu, rm0, 1));
        rm0 = fmaxf(rm0, __shfl_xor_sync(0xffffffffu, rm0, 2));
        rm1 = fmaxf(rm1, __shfl_xor_sync(0xffffffffu, rm1, 1));
        rm1 = fmaxf(rm1, __shfl_xor_sync(0xffffffffu, rm1, 2));
        float mn0 = fmaxf(m0, rm0 * LOG2E);
        float mn1 = fmaxf(m1, rm1 * LOG2E);
        float s0 = fexp2(m0 - mn0);
        float s1 = fexp2(m1 - mn1);
        m0 = mn0; m1 = mn1;
        l0 *= s0; l1 *= s1;
        #pragma unroll
        for (int d = 0; d < 8; d++) {
            oc[d][0] *= s0; oc[d][1] *= s0;
            oc[d][2] *= s1; oc[d][3] *= s1;
        }

        uint32_t pa[4][4];
        float la0 = 0.f, la1 = 0.f;
        #pragma unroll
        for (int nt = 0; nt < 8; nt++) {
            float p0 = fexp2(fmaf(sc[nt][0], LOG2E, -m0));
            float p1 = fexp2(fmaf(sc[nt][1], LOG2E, -m0));
            float p2 = fexp2(fmaf(sc[nt][2], LOG2E, -m1));
            float p3 = fexp2(fmaf(sc[nt][3], LOG2E, -m1));
            la0 += p0 + p1;
            la1 += p2 + p3;
            int ks2 = nt >> 1, idx = (nt & 1) * 2;
            pa[ks2][idx]     = pack_h(p0, p1);
            pa[ks2][idx + 1] = pack_h(p2, p3);
        }
        l0 += la0; l1 += la1;

        // ---- O += P @ V (fp16) ----
        #pragma unroll
        for (int ks2 = 0; ks2 < 4; ks2++) {
            uint32_t v4[4][4];
            #pragma unroll
            for (int dtp = 0; dtp < 4; dtp++) {
                uint32_t ad = kb + ATT_KVS
                    + (uint32_t)((ks2 * 16 + (lane & 15)) * QSTR)
                    + (dtp * 16 + (lane >> 4) * 8) * 2;
                ldsm4t(v4[dtp], ad);
            }
            #pragma unroll
            for (int dtp = 0; dtp < 4; dtp++)
                #pragma unroll
                for (int hf = 0; hf < 2; hf++) {
                    int dt = dtp * 2 + hf, p = hf * 2;
                    mma_f16(oc[dt], pa[ks2], v4[dtp][p], v4[dtp][p + 1]);
                }
        }
    }

    // ---- finalize ----
    l0 += __shfl_xor_sync(0xffffffffu, l0, 1);
    l0 += __shfl_xor_sync(0xffffffffu, l0, 2);
    l1 += __shfl_xor_sync(0xffffffffu, l1, 1);
    l1 += __shfl_xor_sync(0xffffffffu, l1, 2);
    float i0 = 1.f / l0, i1 = 1.f / l1;

    const int b  = bh >> 4;
    const int hh = bh & 15;
    const size_t row0 = (size_t)b * Lx + qb + wid * 16 + (lane >> 2);
    const int colb = hh * 64 + (lane & 3) * 2;
    #pragma unroll
    for (int dt = 0; dt < 8; dt++) {
        float a0 = oc[dt][0] * i0, a1 = oc[dt][1] * i0;
        float a2 = oc[dt][2] * i1, a3 = oc[dt][3] * i1;
        *(uint32_t*)(y_ + row0 * Cx + colb + dt * 8)       = pack_h(a0, a1);
        *(uint32_t*)(y_ + (row0 + 8) * Cx + colb + dt * 8) = pack_h(a2, a3);
    }
}

// ---------------- launcher ----------------
extern "C" void kernel_launch(void* const* d_in, const int* in_sizes, int n_in,
                              void* d_out, int out_size)
{
    const float* x      = (const float*)d_in[0];
    const float* ln1_w  = (const float*)d_in[1];
    const float* ln1_b  = (const float*)d_in[2];
    const float* w_attn = (const float*)d_in[3];
    const float* b_attn = (const float*)d_in[4];
    const float* w_proj = (const float*)d_in[5];
    const float* b_proj = (const float*)d_in[6];
    const float* ln2_w  = (const float*)d_in[7];
    const float* ln2_b  = (const float*)d_in[8];
    const float* w_fc   = (const float*)d_in[9];
    const float* b_fc   = (const float*)d_in[10];
    const float* w_fc2  = (const float*)d_in[11];
    const float* b_fc2  = (const float*)d_in[12];
    float* out = (float*)d_out;

    void *px1, *ph, *py, *pfc, *pq, *pkh, *pvh;
    void *pwah, *pwph, *pwfh, *pw2h;
    cudaGetSymbolAddress(&px1, g_x1);
    cudaGetSymbolAddress(&ph,  g_h);
    cudaGetSymbolAddress(&py,  g_y);
    cudaGetSymbolAddress(&pfc, g_fc);
    cudaGetSymbolAddress(&pq,  g_q);
    cudaGetSymbolAddress(&pkh, g_kh);
    cudaGetSymbolAddress(&pvh, g_vh);
    cudaGetSymbolAddress(&pwah, g_wa_h);
    cudaGetSymbolAddress(&pwph, g_wp_h);
    cudaGetSymbolAddress(&pwfh, g_wf_h);
    cudaGetSymbolAddress(&pw2h, g_w2_h);

    float* x1 = (float*)px1;
    __half* h  = (__half*)ph;
    __half* y  = (__half*)py;
    __half* fc = (__half*)pfc;
    __half* q  = (__half*)pq;
    __half* kh = (__half*)pkh;
    __half* vh = (__half*)pvh;
    __half* wah = (__half*)pwah;
    __half* wph = (__half*)pwph;
    __half* wfh = (__half*)pwfh;
    __half* w2h = (__half*)pw2h;

    static bool attr_done = false;
    if (!attr_done) {
        cudaFuncSetAttribute(mma_gemm<1>, cudaFuncAttributeMaxDynamicSharedMemorySize, GEMM_SMEM);
        cudaFuncSetAttribute(mma_gemm<2>, cudaFuncAttributeMaxDynamicSharedMemorySize, GEMM_SMEM);
        cudaFuncSetAttribute(mma_gemm<3>, cudaFuncAttributeMaxDynamicSharedMemorySize, GEMM_SMEM);
        cudaFuncSetAttribute(attn_mma,    cudaFuncAttributeMaxDynamicSharedMemorySize, ATT_SMEM);
        attr_done = true;
    }

    // 0) weight pre-conversion (fp32 -> fp16, one launch)
    conv_all<<<(N4_TOT + 255)/256, 256>>>(w_attn, w_proj, w_fc, w_fc2);

    // 1) h = LN1(x)
    ln_kernel<<<Mrows, 256>>>(x, ln1_w, ln1_b, h);
    // 2) QKV GEMM -> q (fp16, x0.125) / k / v, [B,H,L,D]
    mma_gemm<3><<<dim3(3*Cx/128, Mrows/128), 128, GEMM_SMEM>>>(
        h, wah, b_attn, nullptr, nullptr, nullptr,
        q, kh, vh, Mrows, 3*Cx, Cx);
    // 3) y = causal flash attention (fp16)
    attn_mma<<<dim3(Lx/64, Bsz*Hx), 128, ATT_SMEM>>>(q, kh, vh, y);
    // 4) x1 = x + y @ w_proj + b_proj
    mma_gemm<2><<<dim3(Cx/128, Mrows/128), 128, GEMM_SMEM>>>(
        y, wph, b_proj, x, x1, nullptr,
        nullptr, nullptr, nullptr, Mrows, Cx, Cx);
    // 5) h = LN2(x1)
    ln_kernel<<<Mrows, 256>>>(x1, ln2_w, ln2_b, h);
    // 6) fc = gelu(h @ w_fc + b_fc) -> fp16
    mma_gemm<1><<<dim3(4*Cx/128, Mrows/128), 128, GEMM_SMEM>>>(
        h, wfh, b_fc, nullptr, nullptr, fc,
        nullptr, nullptr, nullptr, Mrows, 4*Cx, Cx);
    // 7) out = x1 + fc @ w_fc2 + b_fc2
    mma_gemm<2><<<dim3(Cx/128, Mrows/128), 128, GEMM_SMEM>>>(
        fc, w2h, b_fc2, x1, out, nullptr,
        nullptr, nullptr, nullptr, Mrows, Cx, 4*Cx);
}